// round 1
// baseline (speedup 1.0000x reference)
#include <cuda_runtime.h>
#include <cstdint>

#define DD   256
#define NPIX 9216              // 96*96
#define EPSF 2.220446049250313e-16f

#define BM 128
#define BN 128
#define BK 32
#define TM 8
#define TN 8

// ---- device scratch (no allocations allowed) ----
__device__ float  g_xf[DD * NPIX];
__device__ float  g_yf[DD * NPIX];
__device__ float  g_invx[NPIX];
__device__ float  g_invy[NPIX];
__device__ unsigned long long g_best[NPIX];
__device__ int    g_idx[NPIX];
__device__ double g_bsum[DD * NPIX / 256];

__device__ __forceinline__ unsigned int fkey(float v) {
    unsigned int u = __float_as_uint(v);
    return (u & 0x80000000u) ? ~u : (u | 0x80000000u);  // order-preserving float->uint
}

// ---------------------------------------------------------------------------
// 1) per-position squared-norm sums + inv-norms; also reset argmax state
// ---------------------------------------------------------------------------
__global__ void sumsq_kernel(const float* __restrict__ X, const float* __restrict__ Y) {
    int n = blockIdx.x * 256 + threadIdx.x;   // grid 36*256 == NPIX exactly
    float sx = 0.f, sy = 0.f;
#pragma unroll 8
    for (int d = 0; d < DD; d++) {
        float x = X[d * NPIX + n];
        float y = Y[d * NPIX + n];
        sx = fmaf(x, x, sx);
        sy = fmaf(y, y, sy);
    }
    g_invx[n] = 1.0f / (sqrtf(sx) + EPSF);
    g_invy[n] = 1.0f / (sqrtf(sy) + EPSF);
    g_best[n] = 0ull;
}

// ---------------------------------------------------------------------------
// 2) elementwise normalize into aligned scratch
// ---------------------------------------------------------------------------
__global__ void normalize_kernel(const float* __restrict__ X, const float* __restrict__ Y) {
    int e = blockIdx.x * 256 + threadIdx.x;          // float4 index
    if (e >= DD * NPIX / 4) return;
    int i = e * 4;
    int n = i % NPIX;                                 // NPIX % 4 == 0 -> n % 4 == 0
    float4 x  = ((const float4*)X)[e];
    float4 y  = ((const float4*)Y)[e];
    float4 ix = *(const float4*)&g_invx[n];
    float4 iy = *(const float4*)&g_invy[n];
    float4 xo = make_float4(x.x * ix.x, x.y * ix.y, x.z * ix.z, x.w * ix.w);
    float4 yo = make_float4(y.x * iy.x, y.y * iy.y, y.z * iy.z, y.w * iy.w);
    ((float4*)g_xf)[e] = xo;
    ((float4*)g_yf)[e] = yo;
}

// ---------------------------------------------------------------------------
// 3) fused fp32 GEMM (sim = Xf^T * Yf) + row argmax via packed atomicMax
//    Full-rate fp32 via packed fma.rn.f32x2 (FFMA2). A stored dup-packed in SMEM.
// ---------------------------------------------------------------------------
__global__ void __launch_bounds__(256, 2) simargmax_kernel() {
    __shared__ unsigned long long As2[BK][BM];  // each entry = {a, a} packed f32x2
    __shared__ float              Bs[BK][BN];

    const int tid = threadIdx.x;
    const int tx = tid & 15;
    const int ty = tid >> 4;
    const int bm = blockIdx.x;   // n-tile
    const int bn = blockIdx.y;   // m-tile

    const float* A  = g_xf + bm * BM;
    const float* Bp = g_yf + bn * BN;

    unsigned long long acc[TM][TN / 2];
#pragma unroll
    for (int i = 0; i < TM; i++)
#pragma unroll
        for (int j = 0; j < TN / 2; j++) acc[i][j] = 0ull;

    for (int k0 = 0; k0 < DD; k0 += BK) {
#pragma unroll
        for (int it = 0; it < 4; it++) {
            int e  = tid + it * 256;       // float4 slot in BK x BM tile
            int kk = e >> 5;
            int nn = (e & 31) << 2;
            float4 av = *(const float4*)(A  + (k0 + kk) * NPIX + nn);
            float4 bv = *(const float4*)(Bp + (k0 + kk) * NPIX + nn);
            unsigned long long d0, d1, d2, d3;
            asm("mov.b64 %0,{%1,%1};" : "=l"(d0) : "r"(__float_as_uint(av.x)));
            asm("mov.b64 %0,{%1,%1};" : "=l"(d1) : "r"(__float_as_uint(av.y)));
            asm("mov.b64 %0,{%1,%1};" : "=l"(d2) : "r"(__float_as_uint(av.z)));
            asm("mov.b64 %0,{%1,%1};" : "=l"(d3) : "r"(__float_as_uint(av.w)));
            As2[kk][nn + 0] = d0;
            As2[kk][nn + 1] = d1;
            As2[kk][nn + 2] = d2;
            As2[kk][nn + 3] = d3;
            *(float4*)&Bs[kk][nn] = bv;
        }
        __syncthreads();

#pragma unroll
        for (int kk = 0; kk < BK; kk++) {
            const ulonglong2* ap = (const ulonglong2*)&As2[kk][ty * TM];
            ulonglong2 a01 = ap[0], a23 = ap[1], a45 = ap[2], a67 = ap[3];
            unsigned long long a[TM] = {a01.x, a01.y, a23.x, a23.y, a45.x, a45.y, a67.x, a67.y};
            const ulonglong2* bp2 = (const ulonglong2*)&Bs[kk][tx * TN];
            ulonglong2 b01 = bp2[0], b23 = bp2[1];
            unsigned long long b[TN / 2] = {b01.x, b01.y, b23.x, b23.y};
#pragma unroll
            for (int i = 0; i < TM; i++)
#pragma unroll
                for (int j = 0; j < TN / 2; j++)
                    asm("fma.rn.f32x2 %0,%1,%2,%0;" : "+l"(acc[i][j]) : "l"(a[i]), "l"(b[j]));
        }
        __syncthreads();
    }

    // per-row argmax over this thread's 8 columns
    unsigned long long best[TM];
#pragma unroll
    for (int i = 0; i < TM; i++) best[i] = 0ull;
#pragma unroll
    for (int i = 0; i < TM; i++) {
#pragma unroll
        for (int j = 0; j < TN / 2; j++) {
            unsigned int lo = (unsigned int)(acc[i][j] & 0xffffffffull);
            unsigned int hi = (unsigned int)(acc[i][j] >> 32);
            float v0 = __uint_as_float(lo), v1 = __uint_as_float(hi);
            unsigned int m0 = bn * BN + tx * TN + 2 * j;
            unsigned int m1 = m0 + 1;
            unsigned long long p0 = ((unsigned long long)fkey(v0) << 32) | (unsigned int)(~m0);
            unsigned long long p1 = ((unsigned long long)fkey(v1) << 32) | (unsigned int)(~m1);
            if (p0 > best[i]) best[i] = p0;
            if (p1 > best[i]) best[i] = p1;
        }
    }
    // reduce across the 16 tx lanes sharing these rows (lanes 0-15 / 16-31 of the warp)
#pragma unroll
    for (int off = 8; off >= 1; off >>= 1) {
#pragma unroll
        for (int i = 0; i < TM; i++) {
            unsigned long long o = __shfl_xor_sync(0xffffffffu, best[i], off);
            if (o > best[i]) best[i] = o;
        }
    }
    if (tx == 0) {
#pragma unroll
        for (int i = 0; i < TM; i++)
            atomicMax(&g_best[bm * BM + ty * TM + i], best[i]);
    }
}

// ---------------------------------------------------------------------------
// 4) unpack argmax indices
// ---------------------------------------------------------------------------
__global__ void unpack_kernel() {
    int n = blockIdx.x * 256 + threadIdx.x;   // grid 36*256 == NPIX
    g_idx[n] = (int)(~(unsigned int)(g_best[n] & 0xffffffffull));
}

// ---------------------------------------------------------------------------
// 5) gather Y_sel, emit Xf, per-block deterministic loss partials
// ---------------------------------------------------------------------------
__global__ void gather_kernel(float* __restrict__ ysel, float* __restrict__ xf_out) {
    int i = blockIdx.x * 256 + threadIdx.x;   // grid (DD*NPIX/256)
    int n = i % NPIX;
    int idx = g_idx[n];
    float ys = g_yf[i - n + idx];
    float xv = g_xf[i];
    ysel[i]  = ys;
    xf_out[i] = xv;
    float d = xv - ys;
    float sq = d * d;
#pragma unroll
    for (int off = 16; off; off >>= 1) sq += __shfl_xor_sync(0xffffffffu, sq, off);
    __shared__ float w[8];
    if ((threadIdx.x & 31) == 0) w[threadIdx.x >> 5] = sq;
    __syncthreads();
    if (threadIdx.x == 0) {
        float s = 0.f;
#pragma unroll
        for (int k = 0; k < 8; k++) s += w[k];
        g_bsum[blockIdx.x] = (double)s;
    }
}

// ---------------------------------------------------------------------------
// 6) deterministic final loss reduction
// ---------------------------------------------------------------------------
__global__ void finalize_kernel(float* __restrict__ out) {
    __shared__ double sm[256];
    double s = 0.0;
    const int NB = DD * NPIX / 256;
    for (int i = threadIdx.x; i < NB; i += 256) s += g_bsum[i];
    sm[threadIdx.x] = s;
    __syncthreads();
    for (int k = 128; k; k >>= 1) {
        if (threadIdx.x < k) sm[threadIdx.x] += sm[threadIdx.x + k];
        __syncthreads();
    }
    if (threadIdx.x == 0) out[0] = (float)(sm[0] / (double)(DD * NPIX));
}

// ---------------------------------------------------------------------------
extern "C" void kernel_launch(void* const* d_in, const int* in_sizes, int n_in,
                              void* d_out, int out_size) {
    const float* X = (const float*)d_in[0];
    const float* Y = (const float*)d_in[1];
    // d_in[2], d_in[3] (images) are dead inputs: never reach the returned tuple.
    float* out    = (float*)d_out;
    float* ysel   = out + 1;
    float* xf_out = out + 1 + DD * NPIX;

    sumsq_kernel<<<NPIX / 256, 256>>>(X, Y);
    normalize_kernel<<<(DD * NPIX / 4 + 255) / 256, 256>>>(X, Y);
    dim3 g(NPIX / BM, NPIX / BN);
    simargmax_kernel<<<g, 256>>>();
    unpack_kernel<<<NPIX / 256, 256>>>();
    gather_kernel<<<DD * NPIX / 256, 256>>>(ysel, xf_out);
    finalize_kernel<<<1, 256>>>(out);
}

// round 3
// speedup vs baseline: 1.5279x; 1.5279x over previous
#include <cuda_runtime.h>
#include <cuda_fp16.h>
#include <cstdint>

#define DD   256
#define NPIX 9216
#define K3   768                 // 3 x 256 (hi*hi, hi*lo, lo*hi segments)
#define EPSF 2.220446049250313e-16f

#define BM 128
#define BN 256
#define BKH 64                   // fp16 per k-stage (= 128 bytes/row)
#define NKT (K3 / BKH)           // 12
#define NBM (NPIX / BM)          // 72
#define NBN (NPIX / BN)          // 36
#define MARGIN 5e-5f
#define MAXFLAG 1024

// ---------------- device scratch ----------------
__device__ __half g_A[(size_t)NPIX * K3];     // [n][768]
__device__ __half g_B[(size_t)NPIX * K3];     // [m][768]
__device__ float  g_xn[(size_t)NPIX * DD];    // normalized X [n][d] (for fixup)
__device__ float  g_yn[(size_t)NPIX * DD];    // normalized Y [m][d] (for fixup)
__device__ float  g_invx[NPIX];
__device__ float  g_invy[NPIX];
__device__ unsigned long long g_c1[(size_t)NPIX * NBN];  // per (row, n-block) top1 packed
__device__ float  g_c2[(size_t)NPIX * NBN];              // per (row, n-block) top2 value
__device__ int    g_idx[NPIX];
__device__ int    g_flag[MAXFLAG];
__device__ int    g_flagcnt;
__device__ double g_bsum[DD * NPIX / 256];

// ---------------- helpers ----------------
__device__ __forceinline__ uint32_t smem_u32(const void* p) {
    uint32_t a;
    asm("{ .reg .u64 t; cvta.to.shared.u64 t, %1; cvt.u32.u64 %0, t; }" : "=r"(a) : "l"(p));
    return a;
}
#define SW128(off) ((off) ^ (((off) >> 3) & 0x70))

__device__ __forceinline__ unsigned int fkey(float v) {
    unsigned int u = __float_as_uint(v);
    return (u & 0x80000000u) ? ~u : (u | 0x80000000u);
}
__device__ __forceinline__ float unfkey(unsigned int h) {
    return __uint_as_float((h & 0x80000000u) ? (h ^ 0x80000000u) : ~h);
}
__device__ __forceinline__ void cpasync16(uint32_t saddr, const void* g) {
    asm volatile("cp.async.cg.shared.global [%0], [%1], 16;" :: "r"(saddr), "l"(g));
}
#define CP_COMMIT() asm volatile("cp.async.commit_group;" ::: "memory")
#define CP_WAIT1()  asm volatile("cp.async.wait_group 1;" ::: "memory")
#define CP_WAIT0()  asm volatile("cp.async.wait_group 0;" ::: "memory")

__device__ __forceinline__ void ldmatrix_x4(uint32_t* r, uint32_t addr) {
    asm volatile("ldmatrix.sync.aligned.m8n8.x4.shared.b16 {%0,%1,%2,%3}, [%4];"
                 : "=r"(r[0]), "=r"(r[1]), "=r"(r[2]), "=r"(r[3]) : "r"(addr));
}
__device__ __forceinline__ void mma16816(float* c, const uint32_t* a, uint32_t b0, uint32_t b1) {
    asm volatile("mma.sync.aligned.m16n8k16.row.col.f32.f16.f16.f32 "
                 "{%0,%1,%2,%3}, {%4,%5,%6,%7}, {%8,%9}, {%0,%1,%2,%3};"
                 : "+f"(c[0]), "+f"(c[1]), "+f"(c[2]), "+f"(c[3])
                 : "r"(a[0]), "r"(a[1]), "r"(a[2]), "r"(a[3]), "r"(b0), "r"(b1));
}

// ---------------------------------------------------------------------------
// 1) per-position inv-norms; reset flag counter
// ---------------------------------------------------------------------------
__global__ void sumsq_kernel(const float* __restrict__ X, const float* __restrict__ Y) {
    int n = blockIdx.x * 256 + threadIdx.x;
    float sx = 0.f, sy = 0.f;
#pragma unroll 8
    for (int d = 0; d < DD; d++) {
        float x = X[d * NPIX + n];
        float y = Y[d * NPIX + n];
        sx = fmaf(x, x, sx);
        sy = fmaf(y, y, sy);
    }
    g_invx[n] = 1.0f / (sqrtf(sx) + EPSF);
    g_invy[n] = 1.0f / (sqrtf(sy) + EPSF);
    if (blockIdx.x == 0 && threadIdx.x == 0) g_flagcnt = 0;
}

// ---------------------------------------------------------------------------
// 2) normalize + transpose + fp16 split into K=768 operand arrays
//    A' = [Ah | Ah/64 | 64*Al],  B' = [Bh | 64*Bl | Bh/64]
// ---------------------------------------------------------------------------
__global__ void norm_split_kernel(const float* __restrict__ X, const float* __restrict__ Y) {
    __shared__ float s[32][33];
    const bool isB = (blockIdx.z != 0);
    const float* src = isB ? Y : X;
    const float* inv = isB ? g_invy : g_invx;
    float* dstf      = isB ? g_yn : g_xn;
    __half* dsth     = isB ? g_B : g_A;
    int n0 = blockIdx.x * 32, d0 = blockIdx.y * 32;
    int tx = threadIdx.x & 31, ty = threadIdx.x >> 5;
    float iv = inv[n0 + tx];
#pragma unroll
    for (int p = 0; p < 4; p++)
        s[ty + p * 8][tx] = src[(d0 + ty + p * 8) * NPIX + n0 + tx] * iv;
    __syncthreads();
#pragma unroll
    for (int p = 0; p < 4; p++) {
        int n = n0 + ty + p * 8, d = d0 + tx;
        float v = s[tx][ty + p * 8];
        dstf[n * DD + d] = v;
        __half h  = __float2half_rn(v);
        float lo  = v - __half2float(h);
        __half hs = __float2half_rn(v * 0.015625f);   // /64
        __half ls = __float2half_rn(lo * 64.0f);      // *64
        size_t base = (size_t)n * K3 + d;
        dsth[base]       = h;
        dsth[base + 256] = isB ? ls : hs;
        dsth[base + 512] = isB ? hs : ls;
    }
}

// ---------------------------------------------------------------------------
// 3) fp16 mma.sync GEMM (K=768) + fused per-row top-2 over this CTA's 256 cols
//    SMEM: A stages [0,16K)+[16K,32K); B stages [32K,64K)+[64K,96K)
// ---------------------------------------------------------------------------
#define SMEM_GEMM_BYTES 98304

__global__ void __launch_bounds__(256, 1) simgemm_kernel() {
    extern __shared__ char smem[];
    const uint32_t sbase = smem_u32(smem);
    const int tid  = threadIdx.x;
    const int wid  = tid >> 5;
    const int lane = tid & 31;
    const int wm   = wid & 1;          // 2 warps along M
    const int wn   = wid >> 1;         // 4 warps along N
    const int m0   = blockIdx.x * BM;  // X rows
    const int n0   = blockIdx.y * BN;  // Y cols

    float c[4][8][4];
#pragma unroll
    for (int i = 0; i < 4; i++)
#pragma unroll
        for (int j = 0; j < 8; j++)
#pragma unroll
            for (int q = 0; q < 4; q++) c[i][j][q] = 0.f;

    // ---- stage loader ----
    auto load_stage = [&](int kt) {
        const int st = kt & 1;
        const int k0 = kt * BKH;
#pragma unroll
        for (int it = 0; it < 4; it++) {
            int i = tid + it * 256;
            int r = i >> 3, cb = (i & 7) << 4;
            uint32_t sa = sbase + st * 16384 + SW128((uint32_t)(r * 128 + cb));
            const char* ga = (const char*)g_A + ((size_t)(m0 + r) * K3 + k0) * 2 + cb;
            cpasync16(sa, ga);
        }
#pragma unroll
        for (int it = 0; it < 8; it++) {
            int i = tid + it * 256;
            int r = i >> 3, cb = (i & 7) << 4;
            uint32_t sa = sbase + 32768 + st * 32768 + SW128((uint32_t)(r * 128 + cb));
            const char* gb = (const char*)g_B + ((size_t)(n0 + r) * K3 + k0) * 2 + cb;
            cpasync16(sa, gb);
        }
        CP_COMMIT();
    };

    load_stage(0);

    const int arow  = wm * 64 + (lane & 15);
    const int aoff  = ((lane >> 4) << 4);
    const int brow  = wn * 64 + (lane & 7) + ((lane >> 4) << 3);
    const int boff  = (((lane >> 3) & 1) << 4);

    for (int kt = 0; kt < NKT; kt++) {
        if (kt + 1 < NKT) { load_stage(kt + 1); CP_WAIT1(); }
        else              { CP_WAIT0(); }
        __syncthreads();

        const int st = kt & 1;
        const uint32_t aBase = sbase + st * 16384;
        const uint32_t bBase = sbase + 32768 + st * 32768;

#pragma unroll
        for (int kk = 0; kk < 4; kk++) {
            uint32_t af[4][4], bf[4][4];
#pragma unroll
            for (int mt = 0; mt < 4; mt++)
                ldmatrix_x4(af[mt], aBase + SW128((uint32_t)((arow + mt * 16) * 128 + kk * 32 + aoff)));
#pragma unroll
            for (int np = 0; np < 4; np++)
                ldmatrix_x4(bf[np], bBase + SW128((uint32_t)((brow + np * 16) * 128 + kk * 32 + boff)));
#pragma unroll
            for (int mt = 0; mt < 4; mt++)
#pragma unroll
                for (int np = 0; np < 4; np++) {
                    mma16816(c[mt][np * 2],     af[mt], bf[np][0], bf[np][1]);
                    mma16816(c[mt][np * 2 + 1], af[mt], bf[np][2], bf[np][3]);
                }
        }
        __syncthreads();
    }

    // ---- epilogue: per-row top-2 within this CTA's 256 columns ----
    float* sv1 = (float*)smem;                 // [128][4]
    int*   sm1 = (int*)(smem + 2048);          // [128][4]
    float* sv2 = (float*)(smem + 4096);        // [128][4]

#pragma unroll
    for (int mt = 0; mt < 4; mt++) {
#pragma unroll
        for (int p = 0; p < 2; p++) {
            float v1 = -1e30f, v2 = -1e30f;
            int mi = 0x7fffffff;
#pragma unroll
            for (int nt = 0; nt < 8; nt++) {
#pragma unroll
                for (int q = 0; q < 2; q++) {
                    float v = c[mt][nt][p * 2 + q];
                    int m = n0 + wn * 64 + nt * 8 + (lane & 3) * 2 + q;
                    if (v > v1 || (v == v1 && m < mi)) { v2 = v1; v1 = v; mi = m; }
                    else if (v > v2) v2 = v;
                }
            }
            // merge across the 4 lanes holding the same row (lane ^ 1, lane ^ 2)
#pragma unroll
            for (int o = 1; o <= 2; o <<= 1) {
                float ov1 = __shfl_xor_sync(0xffffffffu, v1, o);
                int   omi = __shfl_xor_sync(0xffffffffu, mi, o);
                float ov2 = __shfl_xor_sync(0xffffffffu, v2, o);
                if (ov1 > v1 || (ov1 == v1 && omi < mi)) {
                    v2 = fmaxf(v1, ov2); v1 = ov1; mi = omi;
                } else {
                    v2 = fmaxf(v2, ov1);
                }
            }
            if ((lane & 3) == 0) {
                int rloc = wm * 64 + mt * 16 + (lane >> 2) + p * 8;
                sv1[rloc * 4 + wn] = v1;
                sm1[rloc * 4 + wn] = mi;
                sv2[rloc * 4 + wn] = v2;
            }
        }
    }
    __syncthreads();

    if (tid < 128) {
        float v1 = sv1[tid * 4], v2 = sv2[tid * 4];
        int mi = sm1[tid * 4];
#pragma unroll
        for (int j = 1; j < 4; j++) {
            float bv1 = sv1[tid * 4 + j], bv2 = sv2[tid * 4 + j];
            int bmi = sm1[tid * 4 + j];
            if (bv1 > v1 || (bv1 == v1 && bmi < mi)) {
                v2 = fmaxf(v1, bv2); v1 = bv1; mi = bmi;
            } else {
                v2 = fmaxf(v2, bv1);
            }
        }
        size_t slot = (size_t)(m0 + tid) * NBN + blockIdx.y;
        g_c1[slot] = ((unsigned long long)fkey(v1) << 32) | (unsigned int)(~(unsigned int)mi);
        g_c2[slot] = v2;
    }
}

// ---------------------------------------------------------------------------
// 4) merge per-row candidates across the 36 N-blocks; flag tight rows
// ---------------------------------------------------------------------------
__global__ void merge_kernel() {
    int n = blockIdx.x * 256 + threadIdx.x;
    unsigned long long k1 = 0ull;
#pragma unroll 4
    for (int j = 0; j < NBN; j++) {
        unsigned long long k = g_c1[(size_t)n * NBN + j];
        if (k > k1) k1 = k;
    }
    unsigned int gi = ~(unsigned int)(k1 & 0xffffffffull);
    float gv1 = unfkey((unsigned int)(k1 >> 32));
    float v2 = -1e30f;
#pragma unroll 4
    for (int j = 0; j < NBN; j++) {
        unsigned long long k = g_c1[(size_t)n * NBN + j];
        unsigned int ij = ~(unsigned int)(k & 0xffffffffull);
        float cand = (ij == gi) ? g_c2[(size_t)n * NBN + j] : unfkey((unsigned int)(k >> 32));
        if (cand > v2) v2 = cand;
    }
    g_idx[n] = (int)gi;
    if (gv1 - v2 < MARGIN) {
        int p = atomicAdd(&g_flagcnt, 1);
        if (p < MAXFLAG) g_flag[p] = n;
    }
}

// ---------------------------------------------------------------------------
// 5) fp32 exact-argmax fixup for flagged rows
// ---------------------------------------------------------------------------
__global__ void fixup_kernel() {
    int cnt = g_flagcnt;
    if (cnt > MAXFLAG) cnt = MAXFLAG;
    if (blockIdx.x >= cnt) return;
    int n = g_flag[blockIdx.x];

    __shared__ float xr[DD];
    __shared__ unsigned long long red[128];
    for (int d = threadIdx.x; d < DD; d += 128) xr[d] = g_xn[(size_t)n * DD + d];
    __syncthreads();

    unsigned long long best = 0ull;
    for (int m = threadIdx.x; m < NPIX; m += 128) {
        const float4* yr = (const float4*)&g_yn[(size_t)m * DD];
        float s = 0.f;
#pragma unroll
        for (int d4 = 0; d4 < DD / 4; d4++) {
            float4 y = yr[d4];
            s = fmaf(xr[d4 * 4 + 0], y.x, s);
            s = fmaf(xr[d4 * 4 + 1], y.y, s);
            s = fmaf(xr[d4 * 4 + 2], y.z, s);
            s = fmaf(xr[d4 * 4 + 3], y.w, s);
        }
        unsigned long long k = ((unsigned long long)fkey(s) << 32) | (unsigned int)(~(unsigned int)m);
        if (k > best) best = k;
    }
    red[threadIdx.x] = best;
    __syncthreads();
    for (int k = 64; k; k >>= 1) {
        if (threadIdx.x < k && red[threadIdx.x + k] > red[threadIdx.x])
            red[threadIdx.x] = red[threadIdx.x + k];
        __syncthreads();
    }
    if (threadIdx.x == 0)
        g_idx[n] = (int)(~(unsigned int)(red[0] & 0xffffffffull));
}

// ---------------------------------------------------------------------------
// 6) gather Y_sel, emit Xf, per-block deterministic loss partials
// ---------------------------------------------------------------------------
__global__ void gather_kernel(const float* __restrict__ X, const float* __restrict__ Y,
                              float* __restrict__ ysel, float* __restrict__ xf_out) {
    int i = blockIdx.x * 256 + threadIdx.x;
    int n = i % NPIX;
    int d = i / NPIX;
    float xv = X[i] * g_invx[n];
    int idx = g_idx[n];
    float ys = Y[d * NPIX + idx] * g_invy[idx];
    ysel[i]   = ys;
    xf_out[i] = xv;
    float dd = xv - ys;
    float sq = dd * dd;
#pragma unroll
    for (int off = 16; off; off >>= 1) sq += __shfl_xor_sync(0xffffffffu, sq, off);
    __shared__ float w[8];
    if ((threadIdx.x & 31) == 0) w[threadIdx.x >> 5] = sq;
    __syncthreads();
    if (threadIdx.x == 0) {
        float s = 0.f;
#pragma unroll
        for (int k = 0; k < 8; k++) s += w[k];
        g_bsum[blockIdx.x] = (double)s;
    }
}

// ---------------------------------------------------------------------------
// 7) deterministic final loss reduction
// ---------------------------------------------------------------------------
__global__ void finalize_kernel(float* __restrict__ out) {
    __shared__ double sm[256];
    double s = 0.0;
    const int NB = DD * NPIX / 256;
    for (int i = threadIdx.x; i < NB; i += 256) s += g_bsum[i];
    sm[threadIdx.x] = s;
    __syncthreads();
    for (int k = 128; k; k >>= 1) {
        if (threadIdx.x < k) sm[threadIdx.x] += sm[threadIdx.x + k];
        __syncthreads();
    }
    if (threadIdx.x == 0) out[0] = (float)(sm[0] / (double)(DD * NPIX));
}

// ---------------------------------------------------------------------------
extern "C" void kernel_launch(void* const* d_in, const int* in_sizes, int n_in,
                              void* d_out, int out_size) {
    const float* X = (const float*)d_in[0];
    const float* Y = (const float*)d_in[1];
    // d_in[2], d_in[3] (images) are dead inputs.
    float* out    = (float*)d_out;
    float* ysel   = out + 1;
    float* xf_out = out + 1 + DD * NPIX;

    cudaFuncSetAttribute(simgemm_kernel,
                         cudaFuncAttributeMaxDynamicSharedMemorySize, SMEM_GEMM_BYTES);

    sumsq_kernel<<<NPIX / 256, 256>>>(X, Y);
    norm_split_kernel<<<dim3(NPIX / 32, DD / 32, 2), 256>>>(X, Y);
    simgemm_kernel<<<dim3(NBM, NBN), 256, SMEM_GEMM_BYTES>>>();
    merge_kernel<<<NPIX / 256, 256>>>();
    fixup_kernel<<<MAXFLAG, 128>>>();
    gather_kernel<<<DD * NPIX / 256, 256>>>(X, Y, ysel, xf_out);
    finalize_kernel<<<1, 256>>>(out);
}

// round 4
// speedup vs baseline: 1.5953x; 1.0441x over previous
#include <cuda_runtime.h>
#include <cuda_fp16.h>
#include <cstdint>

#define DD   256
#define NPIX 9216
#define K3   768                 // 3 x 256 (hi*hi, hi*lo, lo*hi segments)
#define EPSF 2.220446049250313e-16f

#define BM 128
#define BN 128
#define BKH 64                   // fp16 per k-stage (= 128 bytes/row)
#define NKT (K3 / BKH)           // 12
#define NBM (NPIX / BM)          // 72
#define NBN (NPIX / BN)          // 72
#define MARGIN 5e-5f
#define MAXFLAG 1024

// ---------------- device scratch ----------------
__device__ __half g_A[(size_t)NPIX * K3];     // [n][768]
__device__ __half g_B[(size_t)NPIX * K3];     // [m][768]
__device__ float  g_xn[(size_t)NPIX * DD];    // normalized X [n][d] (for fixup)
__device__ float  g_yn[(size_t)NPIX * DD];    // normalized Y [m][d] (for fixup)
__device__ float  g_invx[NPIX];
__device__ float  g_invy[NPIX];
__device__ unsigned long long g_c1[(size_t)NPIX * NBN];  // per (row, n-block) top1 packed
__device__ float  g_c2[(size_t)NPIX * NBN];              // per (row, n-block) top2 value
__device__ int    g_idx[NPIX];
__device__ int    g_flag[MAXFLAG];
__device__ int    g_flagcnt;
__device__ double g_bsum[DD * NPIX / 256];

// ---------------- helpers ----------------
__device__ __forceinline__ uint32_t smem_u32(const void* p) {
    uint32_t a;
    asm("{ .reg .u64 t; cvta.to.shared.u64 t, %1; cvt.u32.u64 %0, t; }" : "=r"(a) : "l"(p));
    return a;
}
#define SW128(off) ((off) ^ (((off) >> 3) & 0x70))

__device__ __forceinline__ unsigned int fkey(float v) {
    unsigned int u = __float_as_uint(v);
    return (u & 0x80000000u) ? ~u : (u | 0x80000000u);
}
__device__ __forceinline__ float unfkey(unsigned int h) {
    return __uint_as_float((h & 0x80000000u) ? (h ^ 0x80000000u) : ~h);
}
__device__ __forceinline__ void cpasync16(uint32_t saddr, const void* g) {
    asm volatile("cp.async.cg.shared.global [%0], [%1], 16;" :: "r"(saddr), "l"(g));
}
#define CP_COMMIT() asm volatile("cp.async.commit_group;" ::: "memory")
#define CP_WAIT1()  asm volatile("cp.async.wait_group 1;" ::: "memory")
#define CP_WAIT0()  asm volatile("cp.async.wait_group 0;" ::: "memory")

__device__ __forceinline__ void ldmatrix_x4(uint32_t* r, uint32_t addr) {
    asm volatile("ldmatrix.sync.aligned.m8n8.x4.shared.b16 {%0,%1,%2,%3}, [%4];"
                 : "=r"(r[0]), "=r"(r[1]), "=r"(r[2]), "=r"(r[3]) : "r"(addr));
}
__device__ __forceinline__ void mma16816(float* c, const uint32_t* a, uint32_t b0, uint32_t b1) {
    asm volatile("mma.sync.aligned.m16n8k16.row.col.f32.f16.f16.f32 "
                 "{%0,%1,%2,%3}, {%4,%5,%6,%7}, {%8,%9}, {%0,%1,%2,%3};"
                 : "+f"(c[0]), "+f"(c[1]), "+f"(c[2]), "+f"(c[3])
                 : "r"(a[0]), "r"(a[1]), "r"(a[2]), "r"(a[3]), "r"(b0), "r"(b1));
}

// ---------------------------------------------------------------------------
// 1) per-position inv-norms; reset flag counter
// ---------------------------------------------------------------------------
__global__ void sumsq_kernel(const float* __restrict__ X, const float* __restrict__ Y) {
    int n = blockIdx.x * 256 + threadIdx.x;
    float sx = 0.f, sy = 0.f;
#pragma unroll 8
    for (int d = 0; d < DD; d++) {
        float x = X[d * NPIX + n];
        float y = Y[d * NPIX + n];
        sx = fmaf(x, x, sx);
        sy = fmaf(y, y, sy);
    }
    g_invx[n] = 1.0f / (sqrtf(sx) + EPSF);
    g_invy[n] = 1.0f / (sqrtf(sy) + EPSF);
    if (blockIdx.x == 0 && threadIdx.x == 0) g_flagcnt = 0;
}

// ---------------------------------------------------------------------------
// 2) normalize + transpose + fp16 split into K=768 operand arrays
//    A' = [Ah | Ah/64 | 64*Al],  B' = [Bh | 64*Bl | Bh/64]
// ---------------------------------------------------------------------------
__global__ void norm_split_kernel(const float* __restrict__ X, const float* __restrict__ Y) {
    __shared__ float s[32][33];
    const bool isB = (blockIdx.z != 0);
    const float* src = isB ? Y : X;
    const float* inv = isB ? g_invy : g_invx;
    float* dstf      = isB ? g_yn : g_xn;
    __half* dsth     = isB ? g_B : g_A;
    int n0 = blockIdx.x * 32, d0 = blockIdx.y * 32;
    int tx = threadIdx.x & 31, ty = threadIdx.x >> 5;
    float iv = inv[n0 + tx];
#pragma unroll
    for (int p = 0; p < 4; p++)
        s[ty + p * 8][tx] = src[(d0 + ty + p * 8) * NPIX + n0 + tx] * iv;
    __syncthreads();
#pragma unroll
    for (int p = 0; p < 4; p++) {
        int n = n0 + ty + p * 8, d = d0 + tx;
        float v = s[tx][ty + p * 8];
        dstf[n * DD + d] = v;
        __half h  = __float2half_rn(v);
        float lo  = v - __half2float(h);
        __half hs = __float2half_rn(v * 0.015625f);   // /64
        __half ls = __float2half_rn(lo * 64.0f);      // *64
        size_t base = (size_t)n * K3 + d;
        dsth[base]       = h;
        dsth[base + 256] = isB ? ls : hs;
        dsth[base + 512] = isB ? hs : ls;
    }
}

// ---------------------------------------------------------------------------
// 3) fp16 mma.sync GEMM (K=768, 128x128 tile, occ 2) + fused per-row top-2
//    SMEM: A stages [0,16K)+[16K,32K); B stages [32K,48K)+[48K,64K)
// ---------------------------------------------------------------------------
#define SMEM_GEMM_BYTES 65536

__global__ void __launch_bounds__(256, 2) simgemm_kernel() {
    extern __shared__ char smem[];
    const uint32_t sbase = smem_u32(smem);
    const int tid  = threadIdx.x;
    const int wid  = tid >> 5;
    const int lane = tid & 31;
    const int wm   = wid & 1;          // 2 warps along M
    const int wn   = wid >> 1;         // 4 warps along N (32 cols each)
    const int m0   = blockIdx.x * BM;  // X rows
    const int n0   = blockIdx.y * BN;  // Y cols

    float c[4][4][4];
#pragma unroll
    for (int i = 0; i < 4; i++)
#pragma unroll
        for (int j = 0; j < 4; j++)
#pragma unroll
            for (int q = 0; q < 4; q++) c[i][j][q] = 0.f;

    // ---- stage loader: A 16KB + B 16KB per stage ----
    auto load_stage = [&](int kt) {
        const int st = kt & 1;
        const int k0 = kt * BKH;
#pragma unroll
        for (int it = 0; it < 4; it++) {
            int i = tid + it * 256;
            int r = i >> 3, cb = (i & 7) << 4;
            uint32_t sa = sbase + st * 16384 + SW128((uint32_t)(r * 128 + cb));
            const char* ga = (const char*)g_A + ((size_t)(m0 + r) * K3 + k0) * 2 + cb;
            cpasync16(sa, ga);
        }
#pragma unroll
        for (int it = 0; it < 4; it++) {
            int i = tid + it * 256;
            int r = i >> 3, cb = (i & 7) << 4;
            uint32_t sa = sbase + 32768 + st * 16384 + SW128((uint32_t)(r * 128 + cb));
            const char* gb = (const char*)g_B + ((size_t)(n0 + r) * K3 + k0) * 2 + cb;
            cpasync16(sa, gb);
        }
        CP_COMMIT();
    };

    load_stage(0);

    const int arow = wm * 64 + (lane & 15);
    const int aoff = ((lane >> 4) << 4);
    const int brow = wn * 32 + (lane & 7) + ((lane >> 4) << 3);
    const int boff = (((lane >> 3) & 1) << 4);

    for (int kt = 0; kt < NKT; kt++) {
        if (kt + 1 < NKT) { load_stage(kt + 1); CP_WAIT1(); }
        else              { CP_WAIT0(); }
        __syncthreads();

        const int st = kt & 1;
        const uint32_t aBase = sbase + st * 16384;
        const uint32_t bBase = sbase + 32768 + st * 16384;

#pragma unroll
        for (int kk = 0; kk < 4; kk++) {
            uint32_t af[4][4], bf[2][4];
#pragma unroll
            for (int mt = 0; mt < 4; mt++)
                ldmatrix_x4(af[mt], aBase + SW128((uint32_t)((arow + mt * 16) * 128 + kk * 32 + aoff)));
#pragma unroll
            for (int nb = 0; nb < 2; nb++)
                ldmatrix_x4(bf[nb], bBase + SW128((uint32_t)((brow + nb * 16) * 128 + kk * 32 + boff)));
#pragma unroll
            for (int mt = 0; mt < 4; mt++)
#pragma unroll
                for (int np = 0; np < 4; np++)
                    mma16816(c[mt][np], af[mt], bf[np >> 1][(np & 1) * 2], bf[np >> 1][(np & 1) * 2 + 1]);
        }
        __syncthreads();
    }

    // ---- epilogue: per-row top-2 within this CTA's 128 columns ----
    float* sv1 = (float*)smem;                 // [128][4]
    int*   sm1 = (int*)(smem + 2048);          // [128][4]
    float* sv2 = (float*)(smem + 4096);        // [128][4]

#pragma unroll
    for (int mt = 0; mt < 4; mt++) {
#pragma unroll
        for (int p = 0; p < 2; p++) {
            float v1 = -1e30f, v2 = -1e30f;
            int mi = 0x7fffffff;
#pragma unroll
            for (int nt = 0; nt < 4; nt++) {
#pragma unroll
                for (int q = 0; q < 2; q++) {
                    float v = c[mt][nt][p * 2 + q];
                    int m = n0 + wn * 32 + nt * 8 + (lane & 3) * 2 + q;
                    if (v > v1 || (v == v1 && m < mi)) { v2 = v1; v1 = v; mi = m; }
                    else if (v > v2) v2 = v;
                }
            }
#pragma unroll
            for (int o = 1; o <= 2; o <<= 1) {
                float ov1 = __shfl_xor_sync(0xffffffffu, v1, o);
                int   omi = __shfl_xor_sync(0xffffffffu, mi, o);
                float ov2 = __shfl_xor_sync(0xffffffffu, v2, o);
                if (ov1 > v1 || (ov1 == v1 && omi < mi)) {
                    v2 = fmaxf(v1, ov2); v1 = ov1; mi = omi;
                } else {
                    v2 = fmaxf(v2, ov1);
                }
            }
            if ((lane & 3) == 0) {
                int rloc = wm * 64 + mt * 16 + (lane >> 2) + p * 8;
                sv1[rloc * 4 + wn] = v1;
                sm1[rloc * 4 + wn] = mi;
                sv2[rloc * 4 + wn] = v2;
            }
        }
    }
    __syncthreads();

    if (tid < 128) {
        float v1 = sv1[tid * 4], v2 = sv2[tid * 4];
        int mi = sm1[tid * 4];
#pragma unroll
        for (int j = 1; j < 4; j++) {
            float bv1 = sv1[tid * 4 + j], bv2 = sv2[tid * 4 + j];
            int bmi = sm1[tid * 4 + j];
            if (bv1 > v1 || (bv1 == v1 && bmi < mi)) {
                v2 = fmaxf(v1, bv2); v1 = bv1; mi = bmi;
            } else {
                v2 = fmaxf(v2, bv1);
            }
        }
        size_t slot = (size_t)(m0 + tid) * NBN + blockIdx.y;
        g_c1[slot] = ((unsigned long long)fkey(v1) << 32) | (unsigned int)(~(unsigned int)mi);
        g_c2[slot] = v2;
    }
}

// ---------------------------------------------------------------------------
// 4) merge per-row candidates (4 threads per row); flag tight rows
// ---------------------------------------------------------------------------
__global__ void merge_kernel() {
    int r = threadIdx.x >> 2, l = threadIdx.x & 3;
    int n = blockIdx.x * 64 + r;
    const unsigned long long* row1 = &g_c1[(size_t)n * NBN];
    const float* row2 = &g_c2[(size_t)n * NBN];

    unsigned long long k1 = 0ull;
#pragma unroll 6
    for (int j = l; j < NBN; j += 4) {
        unsigned long long k = row1[j];
        if (k > k1) k1 = k;
    }
#pragma unroll
    for (int o = 1; o <= 2; o <<= 1) {
        unsigned long long ok = __shfl_xor_sync(0xffffffffu, k1, o);
        if (ok > k1) k1 = ok;
    }
    unsigned int gi = ~(unsigned int)(k1 & 0xffffffffull);
    float gv1 = unfkey((unsigned int)(k1 >> 32));
    float v2 = -1e30f;
#pragma unroll 6
    for (int j = l; j < NBN; j += 4) {
        unsigned long long k = row1[j];
        unsigned int ij = ~(unsigned int)(k & 0xffffffffull);
        float cand = (ij == gi) ? row2[j] : unfkey((unsigned int)(k >> 32));
        if (cand > v2) v2 = cand;
    }
#pragma unroll
    for (int o = 1; o <= 2; o <<= 1)
        v2 = fmaxf(v2, __shfl_xor_sync(0xffffffffu, v2, o));
    if (l == 0) {
        g_idx[n] = (int)gi;
        if (gv1 - v2 < MARGIN) {
            int p = atomicAdd(&g_flagcnt, 1);
            if (p < MAXFLAG) g_flag[p] = n;
        }
    }
}

// ---------------------------------------------------------------------------
// 5) fp32 exact-argmax fixup for flagged rows
// ---------------------------------------------------------------------------
__global__ void fixup_kernel() {
    int cnt = g_flagcnt;
    if (cnt > MAXFLAG) cnt = MAXFLAG;
    if (blockIdx.x >= cnt) return;
    int n = g_flag[blockIdx.x];

    __shared__ float xr[DD];
    __shared__ unsigned long long red[128];
    for (int d = threadIdx.x; d < DD; d += 128) xr[d] = g_xn[(size_t)n * DD + d];
    __syncthreads();

    unsigned long long best = 0ull;
    for (int m = threadIdx.x; m < NPIX; m += 128) {
        const float4* yr = (const float4*)&g_yn[(size_t)m * DD];
        float s = 0.f;
#pragma unroll
        for (int d4 = 0; d4 < DD / 4; d4++) {
            float4 y = yr[d4];
            s = fmaf(xr[d4 * 4 + 0], y.x, s);
            s = fmaf(xr[d4 * 4 + 1], y.y, s);
            s = fmaf(xr[d4 * 4 + 2], y.z, s);
            s = fmaf(xr[d4 * 4 + 3], y.w, s);
        }
        unsigned long long k = ((unsigned long long)fkey(s) << 32) | (unsigned int)(~(unsigned int)m);
        if (k > best) best = k;
    }
    red[threadIdx.x] = best;
    __syncthreads();
    for (int k = 64; k; k >>= 1) {
        if (threadIdx.x < k && red[threadIdx.x + k] > red[threadIdx.x])
            red[threadIdx.x] = red[threadIdx.x + k];
        __syncthreads();
    }
    if (threadIdx.x == 0)
        g_idx[n] = (int)(~(unsigned int)(red[0] & 0xffffffffull));
}

// ---------------------------------------------------------------------------
// 6) gather Y_sel, emit Xf, per-block deterministic loss partials
// ---------------------------------------------------------------------------
__global__ void gather_kernel(const float* __restrict__ X, const float* __restrict__ Y,
                              float* __restrict__ ysel, float* __restrict__ xf_out) {
    int i = blockIdx.x * 256 + threadIdx.x;
    int n = i % NPIX;
    int d = i / NPIX;
    float xv = X[i] * g_invx[n];
    int idx = g_idx[n];
    float ys = Y[d * NPIX + idx] * g_invy[idx];
    ysel[i]   = ys;
    xf_out[i] = xv;
    float dd = xv - ys;
    float sq = dd * dd;
#pragma unroll
    for (int off = 16; off; off >>= 1) sq += __shfl_xor_sync(0xffffffffu, sq, off);
    __shared__ float w[8];
    if ((threadIdx.x & 31) == 0) w[threadIdx.x >> 5] = sq;
    __syncthreads();
    if (threadIdx.x == 0) {
        float s = 0.f;
#pragma unroll
        for (int k = 0; k < 8; k++) s += w[k];
        g_bsum[blockIdx.x] = (double)s;
    }
}

// ---------------------------------------------------------------------------
// 7) deterministic final loss reduction
// ---------------------------------------------------------------------------
__global__ void finalize_kernel(float* __restrict__ out) {
    __shared__ double sm[256];
    double s = 0.0;
    const int NB = DD * NPIX / 256;
    for (int i = threadIdx.x; i < NB; i += 256) s += g_bsum[i];
    sm[threadIdx.x] = s;
    __syncthreads();
    for (int k = 128; k; k >>= 1) {
        if (threadIdx.x < k) sm[threadIdx.x] += sm[threadIdx.x + k];
        __syncthreads();
    }
    if (threadIdx.x == 0) out[0] = (float)(sm[0] / (double)(DD * NPIX));
}

// ---------------------------------------------------------------------------
extern "C" void kernel_launch(void* const* d_in, const int* in_sizes, int n_in,
                              void* d_out, int out_size) {
    const float* X = (const float*)d_in[0];
    const float* Y = (const float*)d_in[1];
    // d_in[2], d_in[3] (images) are dead inputs.
    float* out    = (float*)d_out;
    float* ysel   = out + 1;
    float* xf_out = out + 1 + DD * NPIX;

    cudaFuncSetAttribute(simgemm_kernel,
                         cudaFuncAttributeMaxDynamicSharedMemorySize, SMEM_GEMM_BYTES);

    sumsq_kernel<<<NPIX / 256, 256>>>(X, Y);
    norm_split_kernel<<<dim3(NPIX / 32, DD / 32, 2), 256>>>(X, Y);
    simgemm_kernel<<<dim3(NBM, NBN), 256, SMEM_GEMM_BYTES>>>();
    merge_kernel<<<NPIX / 64, 256>>>();
    fixup_kernel<<<MAXFLAG, 128>>>();
    gather_kernel<<<DD * NPIX / 256, 256>>>(X, Y, ysel, xf_out);
    finalize_kernel<<<1, 256>>>(out);
}

// round 5
// speedup vs baseline: 2.0657x; 1.2949x over previous
#include <cuda_runtime.h>
#include <cuda_fp16.h>
#include <cstdint>

#define DD   256
#define NPIX 9216
#define K2   512                 // 2 segments: hi*hi, loA*hiB
#define EPSF 2.220446049250313e-16f

#define BM 128
#define BN 128
#define BKH 64                   // fp16 per k-stage (= 128 bytes/row)
#define NKT (K2 / BKH)           // 8
#define NBM (NPIX / BM)          // 72
#define NBN (NPIX / BN)          // 72
#define MARGIN 1.1e-3f

// ---------------- device scratch ----------------
__device__ __half g_A[(size_t)NPIX * K2];     // [n][512]
__device__ __half g_B[(size_t)NPIX * K2];     // [m][512]
__device__ float  g_xn[(size_t)NPIX * DD];    // normalized X [n][d]
__device__ float  g_yn[(size_t)NPIX * DD];    // normalized Y [m][d]
__device__ float  g_invx[NPIX];
__device__ float  g_invy[NPIX];
__device__ unsigned long long g_c1[(size_t)NPIX * NBN];
__device__ float  g_c2[(size_t)NPIX * NBN];
__device__ int    g_idx[NPIX];
__device__ int    g_flag[NPIX];
__device__ unsigned long long g_fix[NPIX];
__device__ int    g_flagcnt;
__device__ double g_bsum[DD * NPIX / 256];

// ---------------- helpers ----------------
__device__ __forceinline__ uint32_t smem_u32(const void* p) {
    uint32_t a;
    asm("{ .reg .u64 t; cvta.to.shared.u64 t, %1; cvt.u32.u64 %0, t; }" : "=r"(a) : "l"(p));
    return a;
}
#define SW128(off) ((off) ^ (((off) >> 3) & 0x70))

__device__ __forceinline__ unsigned int fkey(float v) {
    unsigned int u = __float_as_uint(v);
    return (u & 0x80000000u) ? ~u : (u | 0x80000000u);
}
__device__ __forceinline__ float unfkey(unsigned int h) {
    return __uint_as_float((h & 0x80000000u) ? (h ^ 0x80000000u) : ~h);
}
__device__ __forceinline__ void cpasync16(uint32_t saddr, const void* g) {
    asm volatile("cp.async.cg.shared.global [%0], [%1], 16;" :: "r"(saddr), "l"(g));
}
#define CP_COMMIT() asm volatile("cp.async.commit_group;" ::: "memory")
#define CP_WAIT1()  asm volatile("cp.async.wait_group 1;" ::: "memory")
#define CP_WAIT0()  asm volatile("cp.async.wait_group 0;" ::: "memory")

__device__ __forceinline__ void ldmatrix_x4(uint32_t* r, uint32_t addr) {
    asm volatile("ldmatrix.sync.aligned.m8n8.x4.shared.b16 {%0,%1,%2,%3}, [%4];"
                 : "=r"(r[0]), "=r"(r[1]), "=r"(r[2]), "=r"(r[3]) : "r"(addr));
}
__device__ __forceinline__ void mma16816(float* c, const uint32_t* a, uint32_t b0, uint32_t b1) {
    asm volatile("mma.sync.aligned.m16n8k16.row.col.f32.f16.f16.f32 "
                 "{%0,%1,%2,%3}, {%4,%5,%6,%7}, {%8,%9}, {%0,%1,%2,%3};"
                 : "+f"(c[0]), "+f"(c[1]), "+f"(c[2]), "+f"(c[3])
                 : "r"(a[0]), "r"(a[1]), "r"(a[2]), "r"(a[3]), "r"(b0), "r"(b1));
}

// ---------------------------------------------------------------------------
// 1) per-position inv-norms; reset flag counter
// ---------------------------------------------------------------------------
__global__ void sumsq_kernel(const float* __restrict__ X, const float* __restrict__ Y) {
    int n = blockIdx.x * 256 + threadIdx.x;
    float sx = 0.f, sy = 0.f;
#pragma unroll 8
    for (int d = 0; d < DD; d++) {
        float x = X[d * NPIX + n];
        float y = Y[d * NPIX + n];
        sx = fmaf(x, x, sx);
        sy = fmaf(y, y, sy);
    }
    g_invx[n] = 1.0f / (sqrtf(sx) + EPSF);
    g_invy[n] = 1.0f / (sqrtf(sy) + EPSF);
    if (blockIdx.x == 0 && threadIdx.x == 0) g_flagcnt = 0;
}

// ---------------------------------------------------------------------------
// 2) normalize + transpose + fp16 split into K=512 operands
//    A' = [Ah | 64*Al],  B' = [Bh | Bh/64]
// ---------------------------------------------------------------------------
__global__ void norm_split_kernel(const float* __restrict__ X, const float* __restrict__ Y) {
    __shared__ float s[32][33];
    const bool isB = (blockIdx.z != 0);
    const float* src = isB ? Y : X;
    const float* inv = isB ? g_invy : g_invx;
    float* dstf      = isB ? g_yn : g_xn;
    __half* dsth     = isB ? g_B : g_A;
    int n0 = blockIdx.x * 32, d0 = blockIdx.y * 32;
    int tx = threadIdx.x & 31, ty = threadIdx.x >> 5;
    float iv = inv[n0 + tx];
#pragma unroll
    for (int p = 0; p < 4; p++)
        s[ty + p * 8][tx] = src[(d0 + ty + p * 8) * NPIX + n0 + tx] * iv;
    __syncthreads();
#pragma unroll
    for (int p = 0; p < 4; p++) {
        int n = n0 + ty + p * 8, d = d0 + tx;
        float v = s[tx][ty + p * 8];
        dstf[n * DD + d] = v;
        __half h = __float2half_rn(v);
        __half seg2;
        if (isB) {
            seg2 = __float2half_rn(__half2float(h) * 0.015625f);   // h/64 (exact scale)
        } else {
            float lo = v - __half2float(h);
            seg2 = __float2half_rn(lo * 64.0f);                    // 64*lo
        }
        size_t base = (size_t)n * K2 + d;
        dsth[base]       = h;
        dsth[base + 256] = seg2;
    }
}

// ---------------------------------------------------------------------------
// 3) fp16 mma.sync GEMM (K=512, 128x128 tile, occ 2) + fused per-row top-2
// ---------------------------------------------------------------------------
#define SMEM_GEMM_BYTES 65536

__global__ void __launch_bounds__(256, 2) simgemm_kernel() {
    extern __shared__ char smem[];
    const uint32_t sbase = smem_u32(smem);
    const int tid  = threadIdx.x;
    const int wid  = tid >> 5;
    const int lane = tid & 31;
    const int wm   = wid & 1;
    const int wn   = wid >> 1;
    const int m0   = blockIdx.x * BM;
    const int n0   = blockIdx.y * BN;

    float c[4][4][4];
#pragma unroll
    for (int i = 0; i < 4; i++)
#pragma unroll
        for (int j = 0; j < 4; j++)
#pragma unroll
            for (int q = 0; q < 4; q++) c[i][j][q] = 0.f;

    auto load_stage = [&](int kt) {
        const int st = kt & 1;
        const int k0 = kt * BKH;
#pragma unroll
        for (int it = 0; it < 4; it++) {
            int i = tid + it * 256;
            int r = i >> 3, cb = (i & 7) << 4;
            uint32_t sa = sbase + st * 16384 + SW128((uint32_t)(r * 128 + cb));
            const char* ga = (const char*)g_A + ((size_t)(m0 + r) * K2 + k0) * 2 + cb;
            cpasync16(sa, ga);
        }
#pragma unroll
        for (int it = 0; it < 4; it++) {
            int i = tid + it * 256;
            int r = i >> 3, cb = (i & 7) << 4;
            uint32_t sa = sbase + 32768 + st * 16384 + SW128((uint32_t)(r * 128 + cb));
            const char* gb = (const char*)g_B + ((size_t)(n0 + r) * K2 + k0) * 2 + cb;
            cpasync16(sa, gb);
        }
        CP_COMMIT();
    };

    load_stage(0);

    const int arow = wm * 64 + (lane & 15);
    const int aoff = ((lane >> 4) << 4);
    const int brow = wn * 32 + (lane & 7) + ((lane >> 4) << 3);
    const int boff = (((lane >> 3) & 1) << 4);

    for (int kt = 0; kt < NKT; kt++) {
        if (kt + 1 < NKT) { load_stage(kt + 1); CP_WAIT1(); }
        else              { CP_WAIT0(); }
        __syncthreads();

        const int st = kt & 1;
        const uint32_t aBase = sbase + st * 16384;
        const uint32_t bBase = sbase + 32768 + st * 16384;

#pragma unroll
        for (int kk = 0; kk < 4; kk++) {
            uint32_t af[4][4], bf[2][4];
#pragma unroll
            for (int mt = 0; mt < 4; mt++)
                ldmatrix_x4(af[mt], aBase + SW128((uint32_t)((arow + mt * 16) * 128 + kk * 32 + aoff)));
#pragma unroll
            for (int nb = 0; nb < 2; nb++)
                ldmatrix_x4(bf[nb], bBase + SW128((uint32_t)((brow + nb * 16) * 128 + kk * 32 + boff)));
#pragma unroll
            for (int mt = 0; mt < 4; mt++)
#pragma unroll
                for (int np = 0; np < 4; np++)
                    mma16816(c[mt][np], af[mt], bf[np >> 1][(np & 1) * 2], bf[np >> 1][(np & 1) * 2 + 1]);
        }
        __syncthreads();
    }

    // ---- epilogue: per-row top-2 within this CTA's 128 columns ----
    float* sv1 = (float*)smem;
    int*   sm1 = (int*)(smem + 2048);
    float* sv2 = (float*)(smem + 4096);

#pragma unroll
    for (int mt = 0; mt < 4; mt++) {
#pragma unroll
        for (int p = 0; p < 2; p++) {
            float v1 = -1e30f, v2 = -1e30f;
            int mi = 0x7fffffff;
#pragma unroll
            for (int nt = 0; nt < 4; nt++) {
#pragma unroll
                for (int q = 0; q < 2; q++) {
                    float v = c[mt][nt][p * 2 + q];
                    int m = n0 + wn * 32 + nt * 8 + (lane & 3) * 2 + q;
                    if (v > v1 || (v == v1 && m < mi)) { v2 = v1; v1 = v; mi = m; }
                    else if (v > v2) v2 = v;
                }
            }
#pragma unroll
            for (int o = 1; o <= 2; o <<= 1) {
                float ov1 = __shfl_xor_sync(0xffffffffu, v1, o);
                int   omi = __shfl_xor_sync(0xffffffffu, mi, o);
                float ov2 = __shfl_xor_sync(0xffffffffu, v2, o);
                if (ov1 > v1 || (ov1 == v1 && omi < mi)) {
                    v2 = fmaxf(v1, ov2); v1 = ov1; mi = omi;
                } else {
                    v2 = fmaxf(v2, ov1);
                }
            }
            if ((lane & 3) == 0) {
                int rloc = wm * 64 + mt * 16 + (lane >> 2) + p * 8;
                sv1[rloc * 4 + wn] = v1;
                sm1[rloc * 4 + wn] = mi;
                sv2[rloc * 4 + wn] = v2;
            }
        }
    }
    __syncthreads();

    if (tid < 128) {
        float v1 = sv1[tid * 4], v2 = sv2[tid * 4];
        int mi = sm1[tid * 4];
#pragma unroll
        for (int j = 1; j < 4; j++) {
            float bv1 = sv1[tid * 4 + j], bv2 = sv2[tid * 4 + j];
            int bmi = sm1[tid * 4 + j];
            if (bv1 > v1 || (bv1 == v1 && bmi < mi)) {
                v2 = fmaxf(v1, bv2); v1 = bv1; mi = bmi;
            } else {
                v2 = fmaxf(v2, bv1);
            }
        }
        size_t slot = (size_t)(m0 + tid) * NBN + blockIdx.y;
        g_c1[slot] = ((unsigned long long)fkey(v1) << 32) | (unsigned int)(~(unsigned int)mi);
        g_c2[slot] = v2;
    }
}

// ---------------------------------------------------------------------------
// 4) merge per-row candidates (4 threads/row); flag rows with tight margin
// ---------------------------------------------------------------------------
__global__ void merge_kernel() {
    int r = threadIdx.x >> 2, l = threadIdx.x & 3;
    int n = blockIdx.x * 64 + r;
    const unsigned long long* row1 = &g_c1[(size_t)n * NBN];
    const float* row2 = &g_c2[(size_t)n * NBN];

    unsigned long long k1 = 0ull;
#pragma unroll 6
    for (int j = l; j < NBN; j += 4) {
        unsigned long long k = row1[j];
        if (k > k1) k1 = k;
    }
#pragma unroll
    for (int o = 1; o <= 2; o <<= 1) {
        unsigned long long ok = __shfl_xor_sync(0xffffffffu, k1, o);
        if (ok > k1) k1 = ok;
    }
    unsigned int gi = ~(unsigned int)(k1 & 0xffffffffull);
    float gv1 = unfkey((unsigned int)(k1 >> 32));
    float v2 = -1e30f;
#pragma unroll 6
    for (int j = l; j < NBN; j += 4) {
        unsigned long long k = row1[j];
        unsigned int ij = ~(unsigned int)(k & 0xffffffffull);
        float cand = (ij == gi) ? row2[j] : unfkey((unsigned int)(k >> 32));
        if (cand > v2) v2 = cand;
    }
#pragma unroll
    for (int o = 1; o <= 2; o <<= 1)
        v2 = fmaxf(v2, __shfl_xor_sync(0xffffffffu, v2, o));
    if (l == 0) {
        g_idx[n] = (int)gi;
        if (gv1 - v2 < MARGIN) {
            g_fix[n] = 0ull;
            int p = atomicAdd(&g_flagcnt, 1);
            g_flag[p] = n;
        }
    }
}

// ---------------------------------------------------------------------------
// 5) batched exact fp32 fixup: 16 flagged rows x 1024 m-columns per CTA
// ---------------------------------------------------------------------------
__global__ void fixup_gemm_kernel() {
    const int cnt = g_flagcnt;
    const int r0 = blockIdx.x * 16;
    if (r0 >= cnt) return;
    const int nrows = min(16, cnt - r0);

    __shared__ float xs[16][DD];                 // 16 KB
    __shared__ unsigned long long sbest[16];

    for (int i = threadIdx.x; i < nrows * DD; i += 256) {
        int r = i >> 8, d = i & 255;
        xs[r][d] = g_xn[(size_t)g_flag[r0 + r] * DD + d];
    }
    if (threadIdx.x < 16) sbest[threadIdx.x] = 0ull;
    __syncthreads();

    unsigned long long best[16];
#pragma unroll
    for (int r = 0; r < 16; r++) best[r] = 0ull;

#pragma unroll
    for (int j = 0; j < 4; j++) {
        int m = blockIdx.y * 1024 + j * 256 + threadIdx.x;
        const float4* yr = (const float4*)&g_yn[(size_t)m * DD];
        float acc[16];
#pragma unroll
        for (int r = 0; r < 16; r++) acc[r] = 0.f;
        for (int d4 = 0; d4 < DD / 4; d4++) {
            float4 y = yr[d4];
#pragma unroll
            for (int r = 0; r < 16; r++) {
                float4 x = *(const float4*)&xs[r][d4 * 4];   // LDS.128 broadcast
                acc[r] = fmaf(x.x, y.x, acc[r]);
                acc[r] = fmaf(x.y, y.y, acc[r]);
                acc[r] = fmaf(x.z, y.z, acc[r]);
                acc[r] = fmaf(x.w, y.w, acc[r]);
            }
        }
#pragma unroll
        for (int r = 0; r < 16; r++) {
            unsigned long long k = ((unsigned long long)fkey(acc[r]) << 32) |
                                   (unsigned int)(~(unsigned int)m);
            if (k > best[r]) best[r] = k;
        }
    }
#pragma unroll
    for (int r = 0; r < 16; r++)
        if (r < nrows) atomicMax(&sbest[r], best[r]);
    __syncthreads();
    if (threadIdx.x < (unsigned)nrows)
        atomicMax(&g_fix[g_flag[r0 + threadIdx.x]], sbest[threadIdx.x]);
}

// ---------------------------------------------------------------------------
// 6) apply fixup results to g_idx
// ---------------------------------------------------------------------------
__global__ void fixup_apply_kernel() {
    int slot = blockIdx.x * 256 + threadIdx.x;
    if (slot < g_flagcnt) {
        int n = g_flag[slot];
        g_idx[n] = (int)(~(unsigned int)(g_fix[n] & 0xffffffffull));
    }
}

// ---------------------------------------------------------------------------
// 7) gather Y_sel, emit Xf, per-block deterministic loss partials
// ---------------------------------------------------------------------------
__global__ void gather_kernel(const float* __restrict__ X, const float* __restrict__ Y,
                              float* __restrict__ ysel, float* __restrict__ xf_out) {
    int i = blockIdx.x * 256 + threadIdx.x;
    int n = i % NPIX;
    int d = i / NPIX;
    float xv = X[i] * g_invx[n];
    int idx = g_idx[n];
    float ys = Y[d * NPIX + idx] * g_invy[idx];
    ysel[i]   = ys;
    xf_out[i] = xv;
    float dd = xv - ys;
    float sq = dd * dd;
#pragma unroll
    for (int off = 16; off; off >>= 1) sq += __shfl_xor_sync(0xffffffffu, sq, off);
    __shared__ float w[8];
    if ((threadIdx.x & 31) == 0) w[threadIdx.x >> 5] = sq;
    __syncthreads();
    if (threadIdx.x == 0) {
        float s = 0.f;
#pragma unroll
        for (int k = 0; k < 8; k++) s += w[k];
        g_bsum[blockIdx.x] = (double)s;
    }
}

// ---------------------------------------------------------------------------
// 8) deterministic final loss reduction
// ---------------------------------------------------------------------------
__global__ void finalize_kernel(float* __restrict__ out) {
    __shared__ double sm[256];
    double s = 0.0;
    const int NB = DD * NPIX / 256;
    for (int i = threadIdx.x; i < NB; i += 256) s += g_bsum[i];
    sm[threadIdx.x] = s;
    __syncthreads();
    for (int k = 128; k; k >>= 1) {
        if (threadIdx.x < k) sm[threadIdx.x] += sm[threadIdx.x + k];
        __syncthreads();
    }
    if (threadIdx.x == 0) out[0] = (float)(sm[0] / (double)(DD * NPIX));
}

// ---------------------------------------------------------------------------
extern "C" void kernel_launch(void* const* d_in, const int* in_sizes, int n_in,
                              void* d_out, int out_size) {
    const float* X = (const float*)d_in[0];
    const float* Y = (const float*)d_in[1];
    // d_in[2], d_in[3] (images) are dead inputs.
    float* out    = (float*)d_out;
    float* ysel   = out + 1;
    float* xf_out = out + 1 + DD * NPIX;

    cudaFuncSetAttribute(simgemm_kernel,
                         cudaFuncAttributeMaxDynamicSharedMemorySize, SMEM_GEMM_BYTES);

    sumsq_kernel<<<NPIX / 256, 256>>>(X, Y);
    norm_split_kernel<<<dim3(NPIX / 32, DD / 32, 2), 256>>>(X, Y);
    simgemm_kernel<<<dim3(NBM, NBN), 256, SMEM_GEMM_BYTES>>>();
    merge_kernel<<<NPIX / 64, 256>>>();
    fixup_gemm_kernel<<<dim3(NPIX / 16, NPIX / 1024), 256>>>();
    fixup_apply_kernel<<<NPIX / 256, 256>>>();
    gather_kernel<<<DD * NPIX / 256, 256>>>(X, Y, ysel, xf_out);
    finalize_kernel<<<1, 256>>>(out);
}

// round 6
// speedup vs baseline: 2.1765x; 1.0536x over previous
#include <cuda_runtime.h>
#include <cuda_fp16.h>
#include <cstdint>

#define DD   256
#define NPIX 9216
#define EPSF 2.220446049250313e-16f

#define BM 128
#define BN 128
#define BKH 64                   // fp16 per k-stage (= 128 bytes/row)
#define NKT (DD / BKH)           // 4
#define NBM (NPIX / BM)          // 72
#define NBN (NPIX / BN)          // 72
#define MARGIN 2.1e-3f           // > 2 * (2^-10 + accum) error bound of hi*hi screen

// ---------------- device scratch ----------------
__device__ __half g_A[(size_t)NPIX * DD];     // fp16(Xn) [n][256]
__device__ __half g_B[(size_t)NPIX * DD];     // fp16(Yn) [m][256]
__device__ float  g_xn[(size_t)NPIX * DD];    // normalized X [n][d]
__device__ float  g_yn[(size_t)NPIX * DD];    // normalized Y [m][d]
__device__ float  g_invx[NPIX];
__device__ float  g_invy[NPIX];
__device__ unsigned long long g_c1[(size_t)NPIX * NBN];
__device__ float  g_c2[(size_t)NPIX * NBN];
__device__ int    g_idx[NPIX];
__device__ int    g_flag[NPIX];
__device__ unsigned long long g_fix[NPIX];
__device__ int    g_flagcnt;
__device__ double g_bsum[DD * NPIX / 256];

// ---------------- helpers ----------------
__device__ __forceinline__ uint32_t smem_u32(const void* p) {
    uint32_t a;
    asm("{ .reg .u64 t; cvta.to.shared.u64 t, %1; cvt.u32.u64 %0, t; }" : "=r"(a) : "l"(p));
    return a;
}
#define SW128(off) ((off) ^ (((off) >> 3) & 0x70))

__device__ __forceinline__ unsigned int fkey(float v) {
    unsigned int u = __float_as_uint(v);
    return (u & 0x80000000u) ? ~u : (u | 0x80000000u);
}
__device__ __forceinline__ float unfkey(unsigned int h) {
    return __uint_as_float((h & 0x80000000u) ? (h ^ 0x80000000u) : ~h);
}
__device__ __forceinline__ void cpasync16(uint32_t saddr, const void* g) {
    asm volatile("cp.async.cg.shared.global [%0], [%1], 16;" :: "r"(saddr), "l"(g));
}
#define CP_COMMIT() asm volatile("cp.async.commit_group;" ::: "memory")
#define CP_WAIT1()  asm volatile("cp.async.wait_group 1;" ::: "memory")
#define CP_WAIT0()  asm volatile("cp.async.wait_group 0;" ::: "memory")

__device__ __forceinline__ void ldmatrix_x4(uint32_t* r, uint32_t addr) {
    asm volatile("ldmatrix.sync.aligned.m8n8.x4.shared.b16 {%0,%1,%2,%3}, [%4];"
                 : "=r"(r[0]), "=r"(r[1]), "=r"(r[2]), "=r"(r[3]) : "r"(addr));
}
__device__ __forceinline__ void mma16816(float* c, const uint32_t* a, uint32_t b0, uint32_t b1) {
    asm volatile("mma.sync.aligned.m16n8k16.row.col.f32.f16.f16.f32 "
                 "{%0,%1,%2,%3}, {%4,%5,%6,%7}, {%8,%9}, {%0,%1,%2,%3};"
                 : "+f"(c[0]), "+f"(c[1]), "+f"(c[2]), "+f"(c[3])
                 : "r"(a[0]), "r"(a[1]), "r"(a[2]), "r"(a[3]), "r"(b0), "r"(b1));
}

// ---------------------------------------------------------------------------
// 1) per-position inv-norms; reset flag counter
// ---------------------------------------------------------------------------
__global__ void sumsq_kernel(const float* __restrict__ X, const float* __restrict__ Y) {
    int n = blockIdx.x * 256 + threadIdx.x;
    float sx = 0.f, sy = 0.f;
#pragma unroll 8
    for (int d = 0; d < DD; d++) {
        float x = X[d * NPIX + n];
        float y = Y[d * NPIX + n];
        sx = fmaf(x, x, sx);
        sy = fmaf(y, y, sy);
    }
    g_invx[n] = 1.0f / (sqrtf(sx) + EPSF);
    g_invy[n] = 1.0f / (sqrtf(sy) + EPSF);
    if (blockIdx.x == 0 && threadIdx.x == 0) g_flagcnt = 0;
}

// ---------------------------------------------------------------------------
// 2) normalize + transpose; emit fp32 [n][d] and fp16 [n][d]
// ---------------------------------------------------------------------------
__global__ void norm_split_kernel(const float* __restrict__ X, const float* __restrict__ Y) {
    __shared__ float s[32][33];
    const bool isB = (blockIdx.z != 0);
    const float* src = isB ? Y : X;
    const float* inv = isB ? g_invy : g_invx;
    float* dstf      = isB ? g_yn : g_xn;
    __half* dsth     = isB ? g_B : g_A;
    int n0 = blockIdx.x * 32, d0 = blockIdx.y * 32;
    int tx = threadIdx.x & 31, ty = threadIdx.x >> 5;
    float iv = inv[n0 + tx];
#pragma unroll
    for (int p = 0; p < 4; p++)
        s[ty + p * 8][tx] = src[(d0 + ty + p * 8) * NPIX + n0 + tx] * iv;
    __syncthreads();
#pragma unroll
    for (int p = 0; p < 4; p++) {
        int n = n0 + ty + p * 8, d = d0 + tx;
        float v = s[tx][ty + p * 8];
        dstf[(size_t)n * DD + d] = v;
        dsth[(size_t)n * DD + d] = __float2half_rn(v);
    }
}

// ---------------------------------------------------------------------------
// 3) fp16 mma.sync GEMM (K=256, 128x128 tile, occ 2) + fused per-row top-2
// ---------------------------------------------------------------------------
#define SMEM_GEMM_BYTES 65536

__global__ void __launch_bounds__(256, 2) simgemm_kernel() {
    extern __shared__ char smem[];
    const uint32_t sbase = smem_u32(smem);
    const int tid  = threadIdx.x;
    const int wid  = tid >> 5;
    const int lane = tid & 31;
    const int wm   = wid & 1;
    const int wn   = wid >> 1;
    const int m0   = blockIdx.x * BM;
    const int n0   = blockIdx.y * BN;

    float c[4][4][4];
#pragma unroll
    for (int i = 0; i < 4; i++)
#pragma unroll
        for (int j = 0; j < 4; j++)
#pragma unroll
            for (int q = 0; q < 4; q++) c[i][j][q] = 0.f;

    auto load_stage = [&](int kt) {
        const int st = kt & 1;
        const int k0 = kt * BKH;
#pragma unroll
        for (int it = 0; it < 4; it++) {
            int i = tid + it * 256;
            int r = i >> 3, cb = (i & 7) << 4;
            uint32_t sa = sbase + st * 16384 + SW128((uint32_t)(r * 128 + cb));
            const char* ga = (const char*)g_A + ((size_t)(m0 + r) * DD + k0) * 2 + cb;
            cpasync16(sa, ga);
        }
#pragma unroll
        for (int it = 0; it < 4; it++) {
            int i = tid + it * 256;
            int r = i >> 3, cb = (i & 7) << 4;
            uint32_t sa = sbase + 32768 + st * 16384 + SW128((uint32_t)(r * 128 + cb));
            const char* gb = (const char*)g_B + ((size_t)(n0 + r) * DD + k0) * 2 + cb;
            cpasync16(sa, gb);
        }
        CP_COMMIT();
    };

    load_stage(0);

    const int arow = wm * 64 + (lane & 15);
    const int aoff = ((lane >> 4) << 4);
    const int brow = wn * 32 + (lane & 7) + ((lane >> 4) << 3);
    const int boff = (((lane >> 3) & 1) << 4);

    for (int kt = 0; kt < NKT; kt++) {
        if (kt + 1 < NKT) { load_stage(kt + 1); CP_WAIT1(); }
        else              { CP_WAIT0(); }
        __syncthreads();

        const int st = kt & 1;
        const uint32_t aBase = sbase + st * 16384;
        const uint32_t bBase = sbase + 32768 + st * 16384;

#pragma unroll
        for (int kk = 0; kk < 4; kk++) {
            uint32_t af[4][4], bf[2][4];
#pragma unroll
            for (int mt = 0; mt < 4; mt++)
                ldmatrix_x4(af[mt], aBase + SW128((uint32_t)((arow + mt * 16) * 128 + kk * 32 + aoff)));
#pragma unroll
            for (int nb = 0; nb < 2; nb++)
                ldmatrix_x4(bf[nb], bBase + SW128((uint32_t)((brow + nb * 16) * 128 + kk * 32 + boff)));
#pragma unroll
            for (int mt = 0; mt < 4; mt++)
#pragma unroll
                for (int np = 0; np < 4; np++)
                    mma16816(c[mt][np], af[mt], bf[np >> 1][(np & 1) * 2], bf[np >> 1][(np & 1) * 2 + 1]);
        }
        __syncthreads();
    }

    // ---- epilogue: per-row top-2 within this CTA's 128 columns ----
    float* sv1 = (float*)smem;
    int*   sm1 = (int*)(smem + 2048);
    float* sv2 = (float*)(smem + 4096);

#pragma unroll
    for (int mt = 0; mt < 4; mt++) {
#pragma unroll
        for (int p = 0; p < 2; p++) {
            float v1 = -1e30f, v2 = -1e30f;
            int mi = 0x7fffffff;
#pragma unroll
            for (int nt = 0; nt < 4; nt++) {
#pragma unroll
                for (int q = 0; q < 2; q++) {
                    float v = c[mt][nt][p * 2 + q];
                    int m = n0 + wn * 32 + nt * 8 + (lane & 3) * 2 + q;
                    if (v > v1 || (v == v1 && m < mi)) { v2 = v1; v1 = v; mi = m; }
                    else if (v > v2) v2 = v;
                }
            }
#pragma unroll
            for (int o = 1; o <= 2; o <<= 1) {
                float ov1 = __shfl_xor_sync(0xffffffffu, v1, o);
                int   omi = __shfl_xor_sync(0xffffffffu, mi, o);
                float ov2 = __shfl_xor_sync(0xffffffffu, v2, o);
                if (ov1 > v1 || (ov1 == v1 && omi < mi)) {
                    v2 = fmaxf(v1, ov2); v1 = ov1; mi = omi;
                } else {
                    v2 = fmaxf(v2, ov1);
                }
            }
            if ((lane & 3) == 0) {
                int rloc = wm * 64 + mt * 16 + (lane >> 2) + p * 8;
                sv1[rloc * 4 + wn] = v1;
                sm1[rloc * 4 + wn] = mi;
                sv2[rloc * 4 + wn] = v2;
            }
        }
    }
    __syncthreads();

    if (tid < 128) {
        float v1 = sv1[tid * 4], v2 = sv2[tid * 4];
        int mi = sm1[tid * 4];
#pragma unroll
        for (int j = 1; j < 4; j++) {
            float bv1 = sv1[tid * 4 + j], bv2 = sv2[tid * 4 + j];
            int bmi = sm1[tid * 4 + j];
            if (bv1 > v1 || (bv1 == v1 && bmi < mi)) {
                v2 = fmaxf(v1, bv2); v1 = bv1; mi = bmi;
            } else {
                v2 = fmaxf(v2, bv1);
            }
        }
        size_t slot = (size_t)(m0 + tid) * NBN + blockIdx.y;
        g_c1[slot] = ((unsigned long long)fkey(v1) << 32) | (unsigned int)(~(unsigned int)mi);
        g_c2[slot] = v2;
    }
}

// ---------------------------------------------------------------------------
// 4) merge per-row candidates (4 threads/row); flag rows with tight margin
// ---------------------------------------------------------------------------
__global__ void merge_kernel() {
    int r = threadIdx.x >> 2, l = threadIdx.x & 3;
    int n = blockIdx.x * 64 + r;
    const unsigned long long* row1 = &g_c1[(size_t)n * NBN];
    const float* row2 = &g_c2[(size_t)n * NBN];

    unsigned long long k1 = 0ull;
#pragma unroll 6
    for (int j = l; j < NBN; j += 4) {
        unsigned long long k = row1[j];
        if (k > k1) k1 = k;
    }
#pragma unroll
    for (int o = 1; o <= 2; o <<= 1) {
        unsigned long long ok = __shfl_xor_sync(0xffffffffu, k1, o);
        if (ok > k1) k1 = ok;
    }
    unsigned int gi = ~(unsigned int)(k1 & 0xffffffffull);
    float gv1 = unfkey((unsigned int)(k1 >> 32));
    float v2 = -1e30f;
#pragma unroll 6
    for (int j = l; j < NBN; j += 4) {
        unsigned long long k = row1[j];
        unsigned int ij = ~(unsigned int)(k & 0xffffffffull);
        float cand = (ij == gi) ? row2[j] : unfkey((unsigned int)(k >> 32));
        if (cand > v2) v2 = cand;
    }
#pragma unroll
    for (int o = 1; o <= 2; o <<= 1)
        v2 = fmaxf(v2, __shfl_xor_sync(0xffffffffu, v2, o));
    if (l == 0) {
        g_idx[n] = (int)gi;
        if (gv1 - v2 < MARGIN) {
            g_fix[n] = 0ull;
            int p = atomicAdd(&g_flagcnt, 1);
            g_flag[p] = n;
        }
    }
}

// ---------------------------------------------------------------------------
// 5) batched exact fp32 fixup (packed f32x2): 16 rows x 1024 m-cols per CTA
//    xs2[p][d] = {x_{2p}[d], x_{2p+1}[d]};  acc2[p] += xs2[p][d] * {y[d],y[d]}
// ---------------------------------------------------------------------------
__global__ void fixup_gemm_kernel() {
    const int cnt = g_flagcnt;
    const int r0 = blockIdx.x * 16;
    if (r0 >= cnt) return;
    const int nrows = min(16, cnt - r0);

    __shared__ unsigned long long xs2[8][DD];    // 16 KB (8 row-pairs, dup-packed)
    __shared__ unsigned long long sbest[16];

    for (int i = threadIdx.x; i < 8 * DD; i += 256) {
        int p = i >> 8, d = i & 255;
        int ra = 2 * p, rb = 2 * p + 1;
        float xa = (ra < nrows) ? g_xn[(size_t)g_flag[r0 + ra] * DD + d] : 0.f;
        float xb = (rb < nrows) ? g_xn[(size_t)g_flag[r0 + rb] * DD + d] : 0.f;
        unsigned long long pk;
        asm("mov.b64 %0,{%1,%2};" : "=l"(pk) : "r"(__float_as_uint(xa)), "r"(__float_as_uint(xb)));
        xs2[p][d] = pk;
    }
    if (threadIdx.x < 16) sbest[threadIdx.x] = 0ull;
    __syncthreads();

    unsigned long long best[16];
#pragma unroll
    for (int r = 0; r < 16; r++) best[r] = 0ull;

#pragma unroll
    for (int j = 0; j < 4; j++) {
        int m = blockIdx.y * 1024 + j * 256 + threadIdx.x;
        const float4* yr = (const float4*)&g_yn[(size_t)m * DD];
        unsigned long long acc2[8];
#pragma unroll
        for (int p = 0; p < 8; p++) acc2[p] = 0ull;
        for (int d4 = 0; d4 < DD / 4; d4++) {
            float4 y = yr[d4];
            unsigned long long y0, y1, y2, y3;
            asm("mov.b64 %0,{%1,%1};" : "=l"(y0) : "r"(__float_as_uint(y.x)));
            asm("mov.b64 %0,{%1,%1};" : "=l"(y1) : "r"(__float_as_uint(y.y)));
            asm("mov.b64 %0,{%1,%1};" : "=l"(y2) : "r"(__float_as_uint(y.z)));
            asm("mov.b64 %0,{%1,%1};" : "=l"(y3) : "r"(__float_as_uint(y.w)));
#pragma unroll
            for (int p = 0; p < 8; p++) {
                ulonglong2 xa = *(const ulonglong2*)&xs2[p][d4 * 4];
                ulonglong2 xb = *(const ulonglong2*)&xs2[p][d4 * 4 + 2];
                asm("fma.rn.f32x2 %0,%1,%2,%0;" : "+l"(acc2[p]) : "l"(xa.x), "l"(y0));
                asm("fma.rn.f32x2 %0,%1,%2,%0;" : "+l"(acc2[p]) : "l"(xa.y), "l"(y1));
                asm("fma.rn.f32x2 %0,%1,%2,%0;" : "+l"(acc2[p]) : "l"(xb.x), "l"(y2));
                asm("fma.rn.f32x2 %0,%1,%2,%0;" : "+l"(acc2[p]) : "l"(xb.y), "l"(y3));
            }
        }
#pragma unroll
        for (int p = 0; p < 8; p++) {
            float va = __uint_as_float((unsigned int)(acc2[p] & 0xffffffffull));
            float vb = __uint_as_float((unsigned int)(acc2[p] >> 32));
            unsigned long long ka = ((unsigned long long)fkey(va) << 32) | (unsigned int)(~(unsigned int)m);
            unsigned long long kb = ((unsigned long long)fkey(vb) << 32) | (unsigned int)(~(unsigned int)m);
            if (ka > best[2 * p])     best[2 * p] = ka;
            if (kb > best[2 * p + 1]) best[2 * p + 1] = kb;
        }
    }
#pragma unroll
    for (int r = 0; r < 16; r++)
        if (r < nrows) atomicMax(&sbest[r], best[r]);
    __syncthreads();
    if (threadIdx.x < (unsigned)nrows)
        atomicMax(&g_fix[g_flag[r0 + threadIdx.x]], sbest[threadIdx.x]);
}

// ---------------------------------------------------------------------------
// 6) apply fixup results to g_idx
// ---------------------------------------------------------------------------
__global__ void fixup_apply_kernel() {
    int slot = blockIdx.x * 256 + threadIdx.x;
    if (slot < g_flagcnt) {
        int n = g_flag[slot];
        g_idx[n] = (int)(~(unsigned int)(g_fix[n] & 0xffffffffull));
    }
}

// ---------------------------------------------------------------------------
// 7) gather Y_sel, emit Xf, per-block deterministic loss partials
// ---------------------------------------------------------------------------
__global__ void gather_kernel(const float* __restrict__ X, const float* __restrict__ Y,
                              float* __restrict__ ysel, float* __restrict__ xf_out) {
    int i = blockIdx.x * 256 + threadIdx.x;
    int n = i % NPIX;
    int d = i / NPIX;
    float xv = X[i] * g_invx[n];
    int idx = g_idx[n];
    float ys = Y[d * NPIX + idx] * g_invy[idx];
    ysel[i]   = ys;
    xf_out[i] = xv;
    float dd = xv - ys;
    float sq = dd * dd;
#pragma unroll
    for (int off = 16; off; off >>= 1) sq += __shfl_xor_sync(0xffffffffu, sq, off);
    __shared__ float w[8];
    if ((threadIdx.x & 31) == 0) w[threadIdx.x >> 5] = sq;
    __syncthreads();
    if (threadIdx.x == 0) {
        float s = 0.f;
#pragma unroll
        for (int k = 0; k < 8; k++) s += w[k];
        g_bsum[blockIdx.x] = (double)s;
    }
}

// ---------------------------------------------------------------------------
// 8) deterministic final loss reduction
// ---------------------------------------------------------------------------
__global__ void finalize_kernel(float* __restrict__ out) {
    __shared__ double sm[256];
    double s = 0.0;
    const int NB = DD * NPIX / 256;
    for (int i = threadIdx.x; i < NB; i += 256) s += g_bsum[i];
    sm[threadIdx.x] = s;
    __syncthreads();
    for (int k = 128; k; k >>= 1) {
        if (threadIdx.x < k) sm[threadIdx.x] += sm[threadIdx.x + k];
        __syncthreads();
    }
    if (threadIdx.x == 0) out[0] = (float)(sm[0] / (double)(DD * NPIX));
}

// ---------------------------------------------------------------------------
extern "C" void kernel_launch(void* const* d_in, const int* in_sizes, int n_in,
                              void* d_out, int out_size) {
    const float* X = (const float*)d_in[0];
    const float* Y = (const float*)d_in[1];
    // d_in[2], d_in[3] (images) are dead inputs.
    float* out    = (float*)d_out;
    float* ysel   = out + 1;
    float* xf_out = out + 1 + DD * NPIX;

    cudaFuncSetAttribute(simgemm_kernel,
                         cudaFuncAttributeMaxDynamicSharedMemorySize, SMEM_GEMM_BYTES);

    sumsq_kernel<<<NPIX / 256, 256>>>(X, Y);
    norm_split_kernel<<<dim3(NPIX / 32, DD / 32, 2), 256>>>(X, Y);
    simgemm_kernel<<<dim3(NBM, NBN), 256, SMEM_GEMM_BYTES>>>();
    merge_kernel<<<NPIX / 64, 256>>>();
    fixup_gemm_kernel<<<dim3(NPIX / 16, NPIX / 1024), 256>>>();
    fixup_apply_kernel<<<NPIX / 256, 256>>>();
    gather_kernel<<<DD * NPIX / 256, 256>>>(X, Y, ysel, xf_out);
    finalize_kernel<<<1, 256>>>(out);
}

// round 7
// speedup vs baseline: 4.3271x; 1.9881x over previous
#include <cuda_runtime.h>
#include <cuda_fp16.h>
#include <cstdint>

#define DD   256
#define NPIX 9216
#define EPSF 2.220446049250313e-16f

#define BM 128
#define BN 128
#define BKH 64                   // fp16 per k-stage (= 128 bytes/row)
#define NKT (DD / BKH)           // 4
#define NBM (NPIX / BM)          // 72
#define NBN (NPIX / BN)          // 72
#define MARGIN 2.1e-3f           // > 2 * (2^-10 + accum) error bound of hi*hi screen

// ---------------- device scratch ----------------
__device__ __half g_A[(size_t)NPIX * DD];     // fp16(Xn) [n][256]
__device__ __half g_B[(size_t)NPIX * DD];     // fp16(Yn) [m][256]
__device__ float  g_xn[(size_t)NPIX * DD];    // normalized X [n][d]
__device__ float  g_yn[(size_t)NPIX * DD];    // normalized Y [m][d]
__device__ float  g_invx[NPIX];
__device__ float  g_invy[NPIX];
__device__ unsigned long long g_c1[(size_t)NPIX * NBN];
__device__ float  g_c2[(size_t)NPIX * NBN];
__device__ int    g_idx[NPIX];
__device__ int    g_flag[NPIX];
__device__ unsigned long long g_fix[NPIX];
__device__ int    g_flagcnt;
__device__ int    g_paircnt;
__device__ int    g_pairs[(size_t)NPIX * NBN / 8];   // (n<<7|j) worklist; ample
__device__ double g_bsum[DD * NPIX / 256];

// ---------------- helpers ----------------
__device__ __forceinline__ uint32_t smem_u32(const void* p) {
    uint32_t a;
    asm("{ .reg .u64 t; cvta.to.shared.u64 t, %1; cvt.u32.u64 %0, t; }" : "=r"(a) : "l"(p));
    return a;
}
#define SW128(off) ((off) ^ (((off) >> 3) & 0x70))

__device__ __forceinline__ unsigned int fkey(float v) {
    unsigned int u = __float_as_uint(v);
    return (u & 0x80000000u) ? ~u : (u | 0x80000000u);
}
__device__ __forceinline__ float unfkey(unsigned int h) {
    return __uint_as_float((h & 0x80000000u) ? (h ^ 0x80000000u) : ~h);
}
__device__ __forceinline__ void cpasync16(uint32_t saddr, const void* g) {
    asm volatile("cp.async.cg.shared.global [%0], [%1], 16;" :: "r"(saddr), "l"(g));
}
#define CP_COMMIT() asm volatile("cp.async.commit_group;" ::: "memory")
#define CP_WAIT1()  asm volatile("cp.async.wait_group 1;" ::: "memory")
#define CP_WAIT0()  asm volatile("cp.async.wait_group 0;" ::: "memory")

__device__ __forceinline__ void ldmatrix_x4(uint32_t* r, uint32_t addr) {
    asm volatile("ldmatrix.sync.aligned.m8n8.x4.shared.b16 {%0,%1,%2,%3}, [%4];"
                 : "=r"(r[0]), "=r"(r[1]), "=r"(r[2]), "=r"(r[3]) : "r"(addr));
}
__device__ __forceinline__ void mma16816(float* c, const uint32_t* a, uint32_t b0, uint32_t b1) {
    asm volatile("mma.sync.aligned.m16n8k16.row.col.f32.f16.f16.f32 "
                 "{%0,%1,%2,%3}, {%4,%5,%6,%7}, {%8,%9}, {%0,%1,%2,%3};"
                 : "+f"(c[0]), "+f"(c[1]), "+f"(c[2]), "+f"(c[3])
                 : "r"(a[0]), "r"(a[1]), "r"(a[2]), "r"(a[3]), "r"(b0), "r"(b1));
}

// ---------------------------------------------------------------------------
// 1) per-position inv-norms; reset counters
// ---------------------------------------------------------------------------
__global__ void sumsq_kernel(const float* __restrict__ X, const float* __restrict__ Y) {
    int n = blockIdx.x * 256 + threadIdx.x;
    float sx = 0.f, sy = 0.f;
#pragma unroll 8
    for (int d = 0; d < DD; d++) {
        float x = X[d * NPIX + n];
        float y = Y[d * NPIX + n];
        sx = fmaf(x, x, sx);
        sy = fmaf(y, y, sy);
    }
    g_invx[n] = 1.0f / (sqrtf(sx) + EPSF);
    g_invy[n] = 1.0f / (sqrtf(sy) + EPSF);
    if (blockIdx.x == 0 && threadIdx.x == 0) { g_flagcnt = 0; g_paircnt = 0; }
}

// ---------------------------------------------------------------------------
// 2) normalize + transpose; emit fp32 [n][d] and fp16 [n][d]
// ---------------------------------------------------------------------------
__global__ void norm_split_kernel(const float* __restrict__ X, const float* __restrict__ Y) {
    __shared__ float s[32][33];
    const bool isB = (blockIdx.z != 0);
    const float* src = isB ? Y : X;
    const float* inv = isB ? g_invy : g_invx;
    float* dstf      = isB ? g_yn : g_xn;
    __half* dsth     = isB ? g_B : g_A;
    int n0 = blockIdx.x * 32, d0 = blockIdx.y * 32;
    int tx = threadIdx.x & 31, ty = threadIdx.x >> 5;
    float iv = inv[n0 + tx];
#pragma unroll
    for (int p = 0; p < 4; p++)
        s[ty + p * 8][tx] = src[(d0 + ty + p * 8) * NPIX + n0 + tx] * iv;
    __syncthreads();
#pragma unroll
    for (int p = 0; p < 4; p++) {
        int n = n0 + ty + p * 8, d = d0 + tx;
        float v = s[tx][ty + p * 8];
        dstf[(size_t)n * DD + d] = v;
        dsth[(size_t)n * DD + d] = __float2half_rn(v);
    }
}

// ---------------------------------------------------------------------------
// 3) fp16 mma.sync GEMM (K=256, 128x128 tile, occ 2) + fused per-row top-2
// ---------------------------------------------------------------------------
#define SMEM_GEMM_BYTES 65536

__global__ void __launch_bounds__(256, 2) simgemm_kernel() {
    extern __shared__ char smem[];
    const uint32_t sbase = smem_u32(smem);
    const int tid  = threadIdx.x;
    const int wid  = tid >> 5;
    const int lane = tid & 31;
    const int wm   = wid & 1;
    const int wn   = wid >> 1;
    const int m0   = blockIdx.x * BM;
    const int n0   = blockIdx.y * BN;

    float c[4][4][4];
#pragma unroll
    for (int i = 0; i < 4; i++)
#pragma unroll
        for (int j = 0; j < 4; j++)
#pragma unroll
            for (int q = 0; q < 4; q++) c[i][j][q] = 0.f;

    auto load_stage = [&](int kt) {
        const int st = kt & 1;
        const int k0 = kt * BKH;
#pragma unroll
        for (int it = 0; it < 4; it++) {
            int i = tid + it * 256;
            int r = i >> 3, cb = (i & 7) << 4;
            uint32_t sa = sbase + st * 16384 + SW128((uint32_t)(r * 128 + cb));
            const char* ga = (const char*)g_A + ((size_t)(m0 + r) * DD + k0) * 2 + cb;
            cpasync16(sa, ga);
        }
#pragma unroll
        for (int it = 0; it < 4; it++) {
            int i = tid + it * 256;
            int r = i >> 3, cb = (i & 7) << 4;
            uint32_t sa = sbase + 32768 + st * 16384 + SW128((uint32_t)(r * 128 + cb));
            const char* gb = (const char*)g_B + ((size_t)(n0 + r) * DD + k0) * 2 + cb;
            cpasync16(sa, gb);
        }
        CP_COMMIT();
    };

    load_stage(0);

    const int arow = wm * 64 + (lane & 15);
    const int aoff = ((lane >> 4) << 4);
    const int brow = wn * 32 + (lane & 7) + ((lane >> 4) << 3);
    const int boff = (((lane >> 3) & 1) << 4);

    for (int kt = 0; kt < NKT; kt++) {
        if (kt + 1 < NKT) { load_stage(kt + 1); CP_WAIT1(); }
        else              { CP_WAIT0(); }
        __syncthreads();

        const int st = kt & 1;
        const uint32_t aBase = sbase + st * 16384;
        const uint32_t bBase = sbase + 32768 + st * 16384;

#pragma unroll
        for (int kk = 0; kk < 4; kk++) {
            uint32_t af[4][4], bf[2][4];
#pragma unroll
            for (int mt = 0; mt < 4; mt++)
                ldmatrix_x4(af[mt], aBase + SW128((uint32_t)((arow + mt * 16) * 128 + kk * 32 + aoff)));
#pragma unroll
            for (int nb = 0; nb < 2; nb++)
                ldmatrix_x4(bf[nb], bBase + SW128((uint32_t)((brow + nb * 16) * 128 + kk * 32 + boff)));
#pragma unroll
            for (int mt = 0; mt < 4; mt++)
#pragma unroll
                for (int np = 0; np < 4; np++)
                    mma16816(c[mt][np], af[mt], bf[np >> 1][(np & 1) * 2], bf[np >> 1][(np & 1) * 2 + 1]);
        }
        __syncthreads();
    }

    // ---- epilogue: per-row top-2 within this CTA's 128 columns ----
    float* sv1 = (float*)smem;
    int*   sm1 = (int*)(smem + 2048);
    float* sv2 = (float*)(smem + 4096);

#pragma unroll
    for (int mt = 0; mt < 4; mt++) {
#pragma unroll
        for (int p = 0; p < 2; p++) {
            float v1 = -1e30f, v2 = -1e30f;
            int mi = 0x7fffffff;
#pragma unroll
            for (int nt = 0; nt < 4; nt++) {
#pragma unroll
                for (int q = 0; q < 2; q++) {
                    float v = c[mt][nt][p * 2 + q];
                    int m = n0 + wn * 32 + nt * 8 + (lane & 3) * 2 + q;
                    if (v > v1 || (v == v1 && m < mi)) { v2 = v1; v1 = v; mi = m; }
                    else if (v > v2) v2 = v;
                }
            }
#pragma unroll
            for (int o = 1; o <= 2; o <<= 1) {
                float ov1 = __shfl_xor_sync(0xffffffffu, v1, o);
                int   omi = __shfl_xor_sync(0xffffffffu, mi, o);
                float ov2 = __shfl_xor_sync(0xffffffffu, v2, o);
                if (ov1 > v1 || (ov1 == v1 && omi < mi)) {
                    v2 = fmaxf(v1, ov2); v1 = ov1; mi = omi;
                } else {
                    v2 = fmaxf(v2, ov1);
                }
            }
            if ((lane & 3) == 0) {
                int rloc = wm * 64 + mt * 16 + (lane >> 2) + p * 8;
                sv1[rloc * 4 + wn] = v1;
                sm1[rloc * 4 + wn] = mi;
                sv2[rloc * 4 + wn] = v2;
            }
        }
    }
    __syncthreads();

    if (tid < 128) {
        float v1 = sv1[tid * 4], v2 = sv2[tid * 4];
        int mi = sm1[tid * 4];
#pragma unroll
        for (int j = 1; j < 4; j++) {
            float bv1 = sv1[tid * 4 + j], bv2 = sv2[tid * 4 + j];
            int bmi = sm1[tid * 4 + j];
            if (bv1 > v1 || (bv1 == v1 && bmi < mi)) {
                v2 = fmaxf(v1, bv2); v1 = bv1; mi = bmi;
            } else {
                v2 = fmaxf(v2, bv1);
            }
        }
        size_t slot = (size_t)(m0 + tid) * NBN + blockIdx.y;
        g_c1[slot] = ((unsigned long long)fkey(v1) << 32) | (unsigned int)(~(unsigned int)mi);
        g_c2[slot] = v2;
    }
}

// ---------------------------------------------------------------------------
// 4) merge per-row candidates (4 threads/row); flag tight rows and emit
//    (row, block) pairs for every block whose top1 is within MARGIN of v1
// ---------------------------------------------------------------------------
__global__ void merge_kernel() {
    int r = threadIdx.x >> 2, l = threadIdx.x & 3;
    int n = blockIdx.x * 64 + r;
    const unsigned long long* row1 = &g_c1[(size_t)n * NBN];
    const float* row2 = &g_c2[(size_t)n * NBN];

    unsigned long long k1 = 0ull;
#pragma unroll 6
    for (int j = l; j < NBN; j += 4) {
        unsigned long long k = row1[j];
        if (k > k1) k1 = k;
    }
#pragma unroll
    for (int o = 1; o <= 2; o <<= 1) {
        unsigned long long ok = __shfl_xor_sync(0xffffffffu, k1, o);
        if (ok > k1) k1 = ok;
    }
    unsigned int gi = ~(unsigned int)(k1 & 0xffffffffull);
    float gv1 = unfkey((unsigned int)(k1 >> 32));
    float v2 = -1e30f;
#pragma unroll 6
    for (int j = l; j < NBN; j += 4) {
        unsigned long long k = row1[j];
        unsigned int ij = ~(unsigned int)(k & 0xffffffffull);
        float cand = (ij == gi) ? row2[j] : unfkey((unsigned int)(k >> 32));
        if (cand > v2) v2 = cand;
    }
#pragma unroll
    for (int o = 1; o <= 2; o <<= 1)
        v2 = fmaxf(v2, __shfl_xor_sync(0xffffffffu, v2, o));

    bool flagged = (gv1 - v2 < MARGIN);
    if (l == 0) {
        g_idx[n] = (int)gi;
        if (flagged) {
            g_fix[n] = 0ull;
            int p = atomicAdd(&g_flagcnt, 1);
            g_flag[p] = n;
        }
    }
    if (flagged) {
        float thresh = gv1 - MARGIN;
#pragma unroll 6
        for (int j = l; j < NBN; j += 4) {
            float bt1 = unfkey((unsigned int)(row1[j] >> 32));
            if (bt1 >= thresh) {
                int p = atomicAdd(&g_paircnt, 1);
                g_pairs[p] = (n << 7) | j;
            }
        }
    }
}

// ---------------------------------------------------------------------------
// 5) candidate-block exact fp32 fixup: one (row, block) pair per iteration;
//    128 threads = 128 m-columns, each an exact 256-MAC dot
// ---------------------------------------------------------------------------
__global__ void fixup_block_kernel() {
    const int cnt = g_paircnt;
    __shared__ float xs[DD];
    __shared__ unsigned long long red[128];

    for (int p = blockIdx.x; p < cnt; p += gridDim.x) {
        int pk = g_pairs[p];
        int n = pk >> 7, j = pk & 127;
        __syncthreads();                      // protect xs across iterations
        if (threadIdx.x < 64)
            *(float4*)&xs[threadIdx.x * 4] =
                *(const float4*)&g_xn[(size_t)n * DD + threadIdx.x * 4];
        __syncthreads();

        int m = j * 128 + threadIdx.x;
        const float4* yr = (const float4*)&g_yn[(size_t)m * DD];
        float s = 0.f;
#pragma unroll
        for (int d4 = 0; d4 < DD / 4; d4++) {
            float4 y = yr[d4];
            s = fmaf(xs[d4 * 4 + 0], y.x, s);
            s = fmaf(xs[d4 * 4 + 1], y.y, s);
            s = fmaf(xs[d4 * 4 + 2], y.z, s);
            s = fmaf(xs[d4 * 4 + 3], y.w, s);
        }
        red[threadIdx.x] = ((unsigned long long)fkey(s) << 32) |
                           (unsigned int)(~(unsigned int)m);
        __syncthreads();
#pragma unroll
        for (int k = 64; k; k >>= 1) {
            if (threadIdx.x < (unsigned)k && red[threadIdx.x + k] > red[threadIdx.x])
                red[threadIdx.x] = red[threadIdx.x + k];
            __syncthreads();
        }
        if (threadIdx.x == 0) atomicMax(&g_fix[n], red[0]);
    }
}

// ---------------------------------------------------------------------------
// 6) apply fixup results to g_idx
// ---------------------------------------------------------------------------
__global__ void fixup_apply_kernel() {
    int slot = blockIdx.x * 256 + threadIdx.x;
    if (slot < g_flagcnt) {
        int n = g_flag[slot];
        g_idx[n] = (int)(~(unsigned int)(g_fix[n] & 0xffffffffull));
    }
}

// ---------------------------------------------------------------------------
// 7) gather Y_sel, emit Xf, per-block deterministic loss partials
// ---------------------------------------------------------------------------
__global__ void gather_kernel(const float* __restrict__ X, const float* __restrict__ Y,
                              float* __restrict__ ysel, float* __restrict__ xf_out) {
    int i = blockIdx.x * 256 + threadIdx.x;
    int n = i % NPIX;
    int d = i / NPIX;
    float xv = X[i] * g_invx[n];
    int idx = g_idx[n];
    float ys = Y[d * NPIX + idx] * g_invy[idx];
    ysel[i]   = ys;
    xf_out[i] = xv;
    float dd = xv - ys;
    float sq = dd * dd;
#pragma unroll
    for (int off = 16; off; off >>= 1) sq += __shfl_xor_sync(0xffffffffu, sq, off);
    __shared__ float w[8];
    if ((threadIdx.x & 31) == 0) w[threadIdx.x >> 5] = sq;
    __syncthreads();
    if (threadIdx.x == 0) {
        float s = 0.f;
#pragma unroll
        for (int k = 0; k < 8; k++) s += w[k];
        g_bsum[blockIdx.x] = (double)s;
    }
}

// ---------------------------------------------------------------------------
// 8) deterministic final loss reduction
// ---------------------------------------------------------------------------
__global__ void finalize_kernel(float* __restrict__ out) {
    __shared__ double sm[256];
    double s = 0.0;
    const int NB = DD * NPIX / 256;
    for (int i = threadIdx.x; i < NB; i += 256) s += g_bsum[i];
    sm[threadIdx.x] = s;
    __syncthreads();
    for (int k = 128; k; k >>= 1) {
        if (threadIdx.x < k) sm[threadIdx.x] += sm[threadIdx.x + k];
        __syncthreads();
    }
    if (threadIdx.x == 0) out[0] = (float)(sm[0] / (double)(DD * NPIX));
}

// ---------------------------------------------------------------------------
extern "C" void kernel_launch(void* const* d_in, const int* in_sizes, int n_in,
                              void* d_out, int out_size) {
    const float* X = (const float*)d_in[0];
    const float* Y = (const float*)d_in[1];
    // d_in[2], d_in[3] (images) are dead inputs.
    float* out    = (float*)d_out;
    float* ysel   = out + 1;
    float* xf_out = out + 1 + DD * NPIX;

    cudaFuncSetAttribute(simgemm_kernel,
                         cudaFuncAttributeMaxDynamicSharedMemorySize, SMEM_GEMM_BYTES);

    sumsq_kernel<<<NPIX / 256, 256>>>(X, Y);
    norm_split_kernel<<<dim3(NPIX / 32, DD / 32, 2), 256>>>(X, Y);
    simgemm_kernel<<<dim3(NBM, NBN), 256, SMEM_GEMM_BYTES>>>();
    merge_kernel<<<NPIX / 64, 256>>>();
    fixup_block_kernel<<<1184, 128>>>();
    fixup_apply_kernel<<<NPIX / 256, 256>>>();
    gather_kernel<<<DD * NPIX / 256, 256>>>(X, Y, ysel, xf_out);
    finalize_kernel<<<1, 256>>>(out);
}

// round 8
// speedup vs baseline: 4.3353x; 1.0019x over previous
#include <cuda_runtime.h>
#include <cuda_fp16.h>
#include <cstdint>

#define DD   256
#define NPIX 9216
#define EPSF 2.220446049250313e-16f

#define BM 128
#define BN 128
#define BKH 64                   // fp16 per k-stage (= 128 bytes/row)
#define NKT (DD / BKH)           // 4
#define NBM (NPIX / BM)          // 72
#define NBN (NPIX / BN)          // 72
#define MARGIN 2.1e-3f           // > 2 * (2^-10 + accum) error bound of hi*hi screen

// ---------------- device scratch ----------------
__device__ __half g_A[(size_t)NPIX * DD];     // fp16(Xn) [n][256]
__device__ __half g_B[(size_t)NPIX * DD];     // fp16(Yn) [m][256]
__device__ float  g_xn[(size_t)NPIX * DD];    // normalized X [n][d]
__device__ float  g_yn[(size_t)NPIX * DD];    // normalized Y [m][d]
__device__ float  g_invx[NPIX];
__device__ float  g_invy[NPIX];
__device__ unsigned long long g_c1[(size_t)NPIX * NBN];
__device__ float  g_c2[(size_t)NPIX * NBN];
__device__ int    g_idx[NPIX];
__device__ int    g_flag[NPIX];
__device__ unsigned long long g_fix[NPIX];
__device__ int    g_flagcnt;
__device__ int    g_paircnt;
__device__ int    g_pairs[(size_t)NPIX * NBN / 8];   // (n<<7|j) worklist; ample
__device__ double g_bsum[DD * NPIX / 256];

// ---------------- helpers ----------------
__device__ __forceinline__ uint32_t smem_u32(const void* p) {
    uint32_t a;
    asm("{ .reg .u64 t; cvta.to.shared.u64 t, %1; cvt.u32.u64 %0, t; }" : "=r"(a) : "l"(p));
    return a;
}
#define SW128(off) ((off) ^ (((off) >> 3) & 0x70))

__device__ __forceinline__ unsigned int fkey(float v) {
    unsigned int u = __float_as_uint(v);
    return (u & 0x80000000u) ? ~u : (u | 0x80000000u);
}
__device__ __forceinline__ float unfkey(unsigned int h) {
    return __uint_as_float((h & 0x80000000u) ? (h ^ 0x80000000u) : ~h);
}
__device__ __forceinline__ void cpasync16(uint32_t saddr, const void* g) {
    asm volatile("cp.async.cg.shared.global [%0], [%1], 16;" :: "r"(saddr), "l"(g));
}
#define CP_COMMIT() asm volatile("cp.async.commit_group;" ::: "memory")
#define CP_WAIT1()  asm volatile("cp.async.wait_group 1;" ::: "memory")
#define CP_WAIT0()  asm volatile("cp.async.wait_group 0;" ::: "memory")

__device__ __forceinline__ void ldmatrix_x4(uint32_t* r, uint32_t addr) {
    asm volatile("ldmatrix.sync.aligned.m8n8.x4.shared.b16 {%0,%1,%2,%3}, [%4];"
                 : "=r"(r[0]), "=r"(r[1]), "=r"(r[2]), "=r"(r[3]) : "r"(addr));
}
__device__ __forceinline__ void mma16816(float* c, const uint32_t* a, uint32_t b0, uint32_t b1) {
    asm volatile("mma.sync.aligned.m16n8k16.row.col.f32.f16.f16.f32 "
                 "{%0,%1,%2,%3}, {%4,%5,%6,%7}, {%8,%9}, {%0,%1,%2,%3};"
                 : "+f"(c[0]), "+f"(c[1]), "+f"(c[2]), "+f"(c[3])
                 : "r"(a[0]), "r"(a[1]), "r"(a[2]), "r"(a[3]), "r"(b0), "r"(b1));
}

// ---------------------------------------------------------------------------
// 1) per-position inv-norms; reset counters
// ---------------------------------------------------------------------------
__global__ void sumsq_kernel(const float* __restrict__ X, const float* __restrict__ Y) {
    int n = blockIdx.x * 256 + threadIdx.x;
    float sx = 0.f, sy = 0.f;
#pragma unroll 8
    for (int d = 0; d < DD; d++) {
        float x = X[d * NPIX + n];
        float y = Y[d * NPIX + n];
        sx = fmaf(x, x, sx);
        sy = fmaf(y, y, sy);
    }
    g_invx[n] = 1.0f / (sqrtf(sx) + EPSF);
    g_invy[n] = 1.0f / (sqrtf(sy) + EPSF);
    if (blockIdx.x == 0 && threadIdx.x == 0) { g_flagcnt = 0; g_paircnt = 0; }
}

// ---------------------------------------------------------------------------
// 2) normalize + transpose; emit fp32 [n][d] and fp16 [n][d]
// ---------------------------------------------------------------------------
__global__ void norm_split_kernel(const float* __restrict__ X, const float* __restrict__ Y) {
    __shared__ float s[32][33];
    const bool isB = (blockIdx.z != 0);
    const float* src = isB ? Y : X;
    const float* inv = isB ? g_invy : g_invx;
    float* dstf      = isB ? g_yn : g_xn;
    __half* dsth     = isB ? g_B : g_A;
    int n0 = blockIdx.x * 32, d0 = blockIdx.y * 32;
    int tx = threadIdx.x & 31, ty = threadIdx.x >> 5;
    float iv = inv[n0 + tx];
#pragma unroll
    for (int p = 0; p < 4; p++)
        s[ty + p * 8][tx] = src[(d0 + ty + p * 8) * NPIX + n0 + tx] * iv;
    __syncthreads();
#pragma unroll
    for (int p = 0; p < 4; p++) {
        int n = n0 + ty + p * 8, d = d0 + tx;
        float v = s[tx][ty + p * 8];
        dstf[(size_t)n * DD + d] = v;
        dsth[(size_t)n * DD + d] = __float2half_rn(v);
    }
}

// ---------------------------------------------------------------------------
// 3) fp16 mma.sync GEMM (K=256, 128x128 tile, 4 warps of 64x64, occ 2)
//    + fused per-row top-2
// ---------------------------------------------------------------------------
#define SMEM_GEMM_BYTES 65536

__global__ void __launch_bounds__(128, 2) simgemm_kernel() {
    extern __shared__ char smem[];
    const uint32_t sbase = smem_u32(smem);
    const int tid  = threadIdx.x;
    const int wid  = tid >> 5;
    const int lane = tid & 31;
    const int wm   = wid & 1;          // 2 warps along M (64 rows each)
    const int wn   = wid >> 1;         // 2 warps along N (64 cols each)
    const int m0   = blockIdx.x * BM;  // X rows
    const int n0   = blockIdx.y * BN;  // Y cols

    float c[4][8][4];                  // [mt][np][q] : 64x64 warp tile
#pragma unroll
    for (int i = 0; i < 4; i++)
#pragma unroll
        for (int j = 0; j < 8; j++)
#pragma unroll
            for (int q = 0; q < 4; q++) c[i][j][q] = 0.f;

    auto load_stage = [&](int kt) {
        const int st = kt & 1;
        const int k0 = kt * BKH;
#pragma unroll
        for (int it = 0; it < 8; it++) {
            int i = tid + it * 128;
            int r = i >> 3, cb = (i & 7) << 4;
            uint32_t sa = sbase + st * 16384 + SW128((uint32_t)(r * 128 + cb));
            const char* ga = (const char*)g_A + ((size_t)(m0 + r) * DD + k0) * 2 + cb;
            cpasync16(sa, ga);
        }
#pragma unroll
        for (int it = 0; it < 8; it++) {
            int i = tid + it * 128;
            int r = i >> 3, cb = (i & 7) << 4;
            uint32_t sa = sbase + 32768 + st * 16384 + SW128((uint32_t)(r * 128 + cb));
            const char* gb = (const char*)g_B + ((size_t)(n0 + r) * DD + k0) * 2 + cb;
            cpasync16(sa, gb);
        }
        CP_COMMIT();
    };

    load_stage(0);

    const int arow = wm * 64 + (lane & 15);
    const int aoff = ((lane >> 4) << 4);
    const int brow = wn * 64 + (lane & 7) + ((lane >> 4) << 3);
    const int boff = (((lane >> 3) & 1) << 4);

    for (int kt = 0; kt < NKT; kt++) {
        if (kt + 1 < NKT) { load_stage(kt + 1); CP_WAIT1(); }
        else              { CP_WAIT0(); }
        __syncthreads();

        const int st = kt & 1;
        const uint32_t aBase = sbase + st * 16384;
        const uint32_t bBase = sbase + 32768 + st * 16384;

#pragma unroll
        for (int kk = 0; kk < 4; kk++) {
            uint32_t af[4][4], bf[4][4];
#pragma unroll
            for (int mt = 0; mt < 4; mt++)
                ldmatrix_x4(af[mt], aBase + SW128((uint32_t)((arow + mt * 16) * 128 + kk * 32 + aoff)));
#pragma unroll
            for (int nb = 0; nb < 4; nb++)
                ldmatrix_x4(bf[nb], bBase + SW128((uint32_t)((brow + nb * 16) * 128 + kk * 32 + boff)));
#pragma unroll
            for (int mt = 0; mt < 4; mt++)
#pragma unroll
                for (int np = 0; np < 8; np++)
                    mma16816(c[mt][np], af[mt], bf[np >> 1][(np & 1) * 2], bf[np >> 1][(np & 1) * 2 + 1]);
        }
        __syncthreads();
    }

    // ---- epilogue: per-row top-2 within this CTA's 128 columns ----
    float* sv1 = (float*)smem;                 // [128][2]
    int*   sm1 = (int*)(smem + 1024);          // [128][2]
    float* sv2 = (float*)(smem + 2048);        // [128][2]

#pragma unroll
    for (int mt = 0; mt < 4; mt++) {
#pragma unroll
        for (int p = 0; p < 2; p++) {
            float v1 = -1e30f, v2 = -1e30f;
            int mi = 0x7fffffff;
#pragma unroll
            for (int np = 0; np < 8; np++) {
#pragma unroll
                for (int q = 0; q < 2; q++) {
                    float v = c[mt][np][p * 2 + q];
                    int m = n0 + wn * 64 + np * 8 + (lane & 3) * 2 + q;
                    if (v > v1 || (v == v1 && m < mi)) { v2 = v1; v1 = v; mi = m; }
                    else if (v > v2) v2 = v;
                }
            }
#pragma unroll
            for (int o = 1; o <= 2; o <<= 1) {
                float ov1 = __shfl_xor_sync(0xffffffffu, v1, o);
                int   omi = __shfl_xor_sync(0xffffffffu, mi, o);
                float ov2 = __shfl_xor_sync(0xffffffffu, v2, o);
                if (ov1 > v1 || (ov1 == v1 && omi < mi)) {
                    v2 = fmaxf(v1, ov2); v1 = ov1; mi = omi;
                } else {
                    v2 = fmaxf(v2, ov1);
                }
            }
            if ((lane & 3) == 0) {
                int rloc = wm * 64 + mt * 16 + (lane >> 2) + p * 8;
                sv1[rloc * 2 + wn] = v1;
                sm1[rloc * 2 + wn] = mi;
                sv2[rloc * 2 + wn] = v2;
            }
        }
    }
    __syncthreads();

    {
        float v1 = sv1[tid * 2], v2 = sv2[tid * 2];
        int mi = sm1[tid * 2];
        float bv1 = sv1[tid * 2 + 1], bv2 = sv2[tid * 2 + 1];
        int bmi = sm1[tid * 2 + 1];
        if (bv1 > v1 || (bv1 == v1 && bmi < mi)) {
            v2 = fmaxf(v1, bv2); v1 = bv1; mi = bmi;
        } else {
            v2 = fmaxf(v2, bv1);
        }
        size_t slot = (size_t)(m0 + tid) * NBN + blockIdx.y;
        g_c1[slot] = ((unsigned long long)fkey(v1) << 32) | (unsigned int)(~(unsigned int)mi);
        g_c2[slot] = v2;
    }
}

// ---------------------------------------------------------------------------
// 4) merge per-row candidates (8 threads/row); flag tight rows and emit
//    (row, block) pairs for every block whose top1 is within MARGIN of v1
// ---------------------------------------------------------------------------
__global__ void merge_kernel() {
    int r = threadIdx.x >> 3, l = threadIdx.x & 7;
    int n = blockIdx.x * 32 + r;
    const unsigned long long* row1 = &g_c1[(size_t)n * NBN];
    const float* row2 = &g_c2[(size_t)n * NBN];

    unsigned long long k1 = 0ull;
#pragma unroll 3
    for (int j = l; j < NBN; j += 8) {
        unsigned long long k = row1[j];
        if (k > k1) k1 = k;
    }
#pragma unroll
    for (int o = 1; o <= 4; o <<= 1) {
        unsigned long long ok = __shfl_xor_sync(0xffffffffu, k1, o);
        if (ok > k1) k1 = ok;
    }
    unsigned int gi = ~(unsigned int)(k1 & 0xffffffffull);
    float gv1 = unfkey((unsigned int)(k1 >> 32));
    float v2 = -1e30f;
#pragma unroll 3
    for (int j = l; j < NBN; j += 8) {
        unsigned long long k = row1[j];
        unsigned int ij = ~(unsigned int)(k & 0xffffffffull);
        float cand = (ij == gi) ? row2[j] : unfkey((unsigned int)(k >> 32));
        if (cand > v2) v2 = cand;
    }
#pragma unroll
    for (int o = 1; o <= 4; o <<= 1)
        v2 = fmaxf(v2, __shfl_xor_sync(0xffffffffu, v2, o));

    bool flagged = (gv1 - v2 < MARGIN);
    if (l == 0) {
        g_idx[n] = (int)gi;
        if (flagged) {
            g_fix[n] = 0ull;
            int p = atomicAdd(&g_flagcnt, 1);
            g_flag[p] = n;
        }
    }
    if (flagged) {
        float thresh = gv1 - MARGIN;
#pragma unroll 3
        for (int j = l; j < NBN; j += 8) {
            float bt1 = unfkey((unsigned int)(row1[j] >> 32));
            if (bt1 >= thresh) {
                int p = atomicAdd(&g_paircnt, 1);
                g_pairs[p] = (n << 7) | j;
            }
        }
    }
}

// ---------------------------------------------------------------------------
// 5) candidate-block exact fp32 fixup: one (row, block) pair per iteration;
//    128 threads = 128 m-columns, each an exact 256-MAC dot
// ---------------------------------------------------------------------------
__global__ void fixup_block_kernel() {
    const int cnt = g_paircnt;
    __shared__ float xs[DD];
    __shared__ unsigned long long red[128];

    for (int p = blockIdx.x; p < cnt; p += gridDim.x) {
        int pk = g_pairs[p];
        int n = pk >> 7, j = pk & 127;
        __syncthreads();                      // protect xs across iterations
        if (threadIdx.x < 64)
            *(float4*)&xs[threadIdx.x * 4] =
                *(const float4*)&g_xn[(size_t)n * DD + threadIdx.x * 4];
        __syncthreads();

        int m = j * 128 + threadIdx.x;
        const float4* yr = (const float4*)&g_yn[(size_t)m * DD];
        float s = 0.f;
#pragma unroll
        for (int d4 = 0; d4 < DD / 4; d4++) {
            float4 y = yr[d4];
            s = fmaf(xs[d4 * 4 + 0], y.x, s);
            s = fmaf(xs[d4 * 4 + 1], y.y, s);
            s = fmaf(xs[d4 * 4 + 2], y.z, s);
            s = fmaf(xs[d4 * 4 + 3], y.w, s);
        }
        red[threadIdx.x] = ((unsigned long long)fkey(s) << 32) |
                           (unsigned int)(~(unsigned int)m);
        __syncthreads();
#pragma unroll
        for (int k = 64; k; k >>= 1) {
            if (threadIdx.x < (unsigned)k && red[threadIdx.x + k] > red[threadIdx.x])
                red[threadIdx.x] = red[threadIdx.x + k];
            __syncthreads();
        }
        if (threadIdx.x == 0) atomicMax(&g_fix[n], red[0]);
    }
}

// ---------------------------------------------------------------------------
// 6) apply fixup results to g_idx
// ---------------------------------------------------------------------------
__global__ void fixup_apply_kernel() {
    int slot = blockIdx.x * 256 + threadIdx.x;
    if (slot < g_flagcnt) {
        int n = g_flag[slot];
        g_idx[n] = (int)(~(unsigned int)(g_fix[n] & 0xffffffffull));
    }
}

// ---------------------------------------------------------------------------
// 7) gather Y_sel, emit Xf, per-block deterministic loss partials
// ---------------------------------------------------------------------------
__global__ void gather_kernel(const float* __restrict__ X, const float* __restrict__ Y,
                              float* __restrict__ ysel, float* __restrict__ xf_out) {
    int i = blockIdx.x * 256 + threadIdx.x;
    int n = i % NPIX;
    int d = i / NPIX;
    float xv = X[i] * g_invx[n];
    int idx = g_idx[n];
    float ys = Y[d * NPIX + idx] * g_invy[idx];
    ysel[i]   = ys;
    xf_out[i] = xv;
    float dd = xv - ys;
    float sq = dd * dd;
#pragma unroll
    for (int off = 16; off; off >>= 1) sq += __shfl_xor_sync(0xffffffffu, sq, off);
    __shared__ float w[8];
    if ((threadIdx.x & 31) == 0) w[threadIdx.x >> 5] = sq;
    __syncthreads();
    if (threadIdx.x == 0) {
        float s = 0.f;
#pragma unroll
        for (int k = 0; k < 8; k++) s += w[k];
        g_bsum[blockIdx.x] = (double)s;
    }
}

// ---------------------------------------------------------------------------
// 8) deterministic final loss reduction
// ---------------------------------------------------------------------------
__global__ void finalize_kernel(float* __restrict__ out) {
    __shared__ double sm[256];
    double s = 0.0;
    const int NB = DD * NPIX / 256;
    for (int i = threadIdx.x; i < NB; i += 256) s += g_bsum[i];
    sm[threadIdx.x] = s;
    __syncthreads();
    for (int k = 128; k; k >>= 1) {
        if (threadIdx.x < k) sm[threadIdx.x] += sm[threadIdx.x + k];
        __syncthreads();
    }
    if (threadIdx.x == 0) out[0] = (float)(sm[0] / (double)(DD * NPIX));
}

// ---------------------------------------------------------------------------
extern "C" void kernel_launch(void* const* d_in, const int* in_sizes, int n_in,
                              void* d_out, int out_size) {
    const float* X = (const float*)d_in[0];
    const float* Y = (const float*)d_in[1];
    // d_in[2], d_in[3] (images) are dead inputs.
    float* out    = (float*)d_out;
    float* ysel   = out + 1;
    float* xf_out = out + 1 + DD * NPIX;

    cudaFuncSetAttribute(simgemm_kernel,
                         cudaFuncAttributeMaxDynamicSharedMemorySize, SMEM_GEMM_BYTES);

    sumsq_kernel<<<NPIX / 256, 256>>>(X, Y);
    norm_split_kernel<<<dim3(NPIX / 32, DD / 32, 2), 256>>>(X, Y);
    simgemm_kernel<<<dim3(NBM, NBN), 128, SMEM_GEMM_BYTES>>>();
    merge_kernel<<<NPIX / 32, 256>>>();
    fixup_block_kernel<<<1184, 128>>>();
    fixup_apply_kernel<<<NPIX / 256, 256>>>();
    gather_kernel<<<DD * NPIX / 256, 256>>>(X, Y, ysel, xf_out);
    finalize_kernel<<<1, 256>>>(out);
}

// round 9
// speedup vs baseline: 4.7480x; 1.0952x over previous
#include <cuda_runtime.h>
#include <cuda_fp16.h>
#include <cstdint>

#define DD   256
#define NPIX 9216
#define EPSF 2.220446049250313e-16f

#define BM 128
#define BN 128
#define BKH 64                   // fp16 per k-stage (= 128 bytes/row)
#define NKT (DD / BKH)           // 4
#define NBM (NPIX / BM)          // 72
#define NBN (NPIX / BN)          // 72
#define MARGIN 2.1e-3f           // > 2 * (2^-10 + accum) error bound of hi*hi screen

// ---------------- device scratch ----------------
__device__ __half g_A[(size_t)NPIX * DD];     // fp16(Xn) [n][256]
__device__ __half g_B[(size_t)NPIX * DD];     // fp16(Yn) [m][256]
__device__ float  g_xn[(size_t)NPIX * DD];    // normalized X [n][d]
__device__ float  g_yn[(size_t)NPIX * DD];    // normalized Y [m][d]
__device__ unsigned long long g_c1[(size_t)NPIX * NBN];
__device__ float  g_c2[(size_t)NPIX * NBN];
__device__ int    g_idx[NPIX];
__device__ int    g_flag[NPIX];
__device__ unsigned long long g_fix[NPIX];
__device__ int    g_flagcnt;
__device__ int    g_paircnt;
__device__ int    g_pairs[(size_t)NPIX * NBN / 8];   // (n<<7|j) worklist; ample
__device__ double g_bsum[DD * NPIX / 1024];

// ---------------- helpers ----------------
__device__ __forceinline__ uint32_t smem_u32(const void* p) {
    uint32_t a;
    asm("{ .reg .u64 t; cvta.to.shared.u64 t, %1; cvt.u32.u64 %0, t; }" : "=r"(a) : "l"(p));
    return a;
}
#define SW128(off) ((off) ^ (((off) >> 3) & 0x70))

__device__ __forceinline__ unsigned int fkey(float v) {
    unsigned int u = __float_as_uint(v);
    return (u & 0x80000000u) ? ~u : (u | 0x80000000u);
}
__device__ __forceinline__ float unfkey(unsigned int h) {
    return __uint_as_float((h & 0x80000000u) ? (h ^ 0x80000000u) : ~h);
}
__device__ __forceinline__ void cpasync16(uint32_t saddr, const void* g) {
    asm volatile("cp.async.cg.shared.global [%0], [%1], 16;" :: "r"(saddr), "l"(g));
}
#define CP_COMMIT() asm volatile("cp.async.commit_group;" ::: "memory")
#define CP_WAIT1()  asm volatile("cp.async.wait_group 1;" ::: "memory")
#define CP_WAIT0()  asm volatile("cp.async.wait_group 0;" ::: "memory")

__device__ __forceinline__ void ldmatrix_x4(uint32_t* r, uint32_t addr) {
    asm volatile("ldmatrix.sync.aligned.m8n8.x4.shared.b16 {%0,%1,%2,%3}, [%4];"
                 : "=r"(r[0]), "=r"(r[1]), "=r"(r[2]), "=r"(r[3]) : "r"(addr));
}
__device__ __forceinline__ void mma16816(float* c, const uint32_t* a, uint32_t b0, uint32_t b1) {
    asm volatile("mma.sync.aligned.m16n8k16.row.col.f32.f16.f16.f32 "
                 "{%0,%1,%2,%3}, {%4,%5,%6,%7}, {%8,%9}, {%0,%1,%2,%3};"
                 : "+f"(c[0]), "+f"(c[1]), "+f"(c[2]), "+f"(c[3])
                 : "r"(a[0]), "r"(a[1]), "r"(a[2]), "r"(a[3]), "r"(b0), "r"(b1));
}

// ---------------------------------------------------------------------------
// 1) fused: load 256d x 32n tile, compute inv-norms, emit normalized fp32+fp16
//    (transposed [n][d]) and, for X, the Xf output [d][n]. Resets counters.
// ---------------------------------------------------------------------------
__global__ void __launch_bounds__(256) norm_all_kernel(const float* __restrict__ X,
                                                       const float* __restrict__ Y,
                                                       float* __restrict__ xf_out) {
    __shared__ float s[256][33];     // [d][n_local], padded
    __shared__ float psum[8][32];
    __shared__ float ivs[32];
    const bool isB = (blockIdx.y != 0);
    const float* src = isB ? Y : X;
    float* dstf      = isB ? g_yn : g_xn;
    __half* dsth     = isB ? g_B : g_A;
    const int n0 = blockIdx.x * 32;
    const int tx = threadIdx.x & 31, ty = threadIdx.x >> 5;

    if (blockIdx.x == 0 && blockIdx.y == 0 && threadIdx.x == 0) {
        g_flagcnt = 0; g_paircnt = 0;
    }

    float acc = 0.f;
#pragma unroll
    for (int p = 0; p < 32; p++) {
        int d = ty * 32 + p;
        float v = src[(size_t)d * NPIX + n0 + tx];
        s[d][tx] = v;
        acc = fmaf(v, v, acc);
    }
    psum[ty][tx] = acc;
    __syncthreads();
    if (ty == 0) {
        float t = 0.f;
#pragma unroll
        for (int w = 0; w < 8; w++) t += psum[w][tx];
        ivs[tx] = 1.0f / (sqrtf(t) + EPSF);
    }
    __syncthreads();

    // transposed outputs [n][d], coalesced in d
#pragma unroll
    for (int nl = ty; nl < 32; nl += 8) {
        float iv = ivs[nl];
        size_t base = (size_t)(n0 + nl) * DD;
#pragma unroll
        for (int q = 0; q < 8; q++) {
            int d = q * 32 + tx;
            float v = s[d][nl] * iv;
            dstf[base + d] = v;
            dsth[base + d] = __float2half_rn(v);
        }
    }
    // Xf output [d][n], coalesced in n
    if (!isB) {
        float iv = ivs[tx];
#pragma unroll
        for (int p = 0; p < 32; p++) {
            int d = ty * 32 + p;
            xf_out[(size_t)d * NPIX + n0 + tx] = s[d][tx] * iv;
        }
    }
}

// ---------------------------------------------------------------------------
// 2) fp16 mma.sync GEMM (K=256, 128x128 tile, 4 warps of 64x64, occ 2)
//    + fused per-row top-2
// ---------------------------------------------------------------------------
#define SMEM_GEMM_BYTES 65536

__global__ void __launch_bounds__(128, 2) simgemm_kernel() {
    extern __shared__ char smem[];
    const uint32_t sbase = smem_u32(smem);
    const int tid  = threadIdx.x;
    const int wid  = tid >> 5;
    const int lane = tid & 31;
    const int wm   = wid & 1;
    const int wn   = wid >> 1;
    const int m0   = blockIdx.x * BM;
    const int n0   = blockIdx.y * BN;

    float c[4][8][4];
#pragma unroll
    for (int i = 0; i < 4; i++)
#pragma unroll
        for (int j = 0; j < 8; j++)
#pragma unroll
            for (int q = 0; q < 4; q++) c[i][j][q] = 0.f;

    auto load_stage = [&](int kt) {
        const int st = kt & 1;
        const int k0 = kt * BKH;
#pragma unroll
        for (int it = 0; it < 8; it++) {
            int i = tid + it * 128;
            int r = i >> 3, cb = (i & 7) << 4;
            uint32_t sa = sbase + st * 16384 + SW128((uint32_t)(r * 128 + cb));
            const char* ga = (const char*)g_A + ((size_t)(m0 + r) * DD + k0) * 2 + cb;
            cpasync16(sa, ga);
        }
#pragma unroll
        for (int it = 0; it < 8; it++) {
            int i = tid + it * 128;
            int r = i >> 3, cb = (i & 7) << 4;
            uint32_t sa = sbase + 32768 + st * 16384 + SW128((uint32_t)(r * 128 + cb));
            const char* gb = (const char*)g_B + ((size_t)(n0 + r) * DD + k0) * 2 + cb;
            cpasync16(sa, gb);
        }
        CP_COMMIT();
    };

    load_stage(0);

    const int arow = wm * 64 + (lane & 15);
    const int aoff = ((lane >> 4) << 4);
    const int brow = wn * 64 + (lane & 7) + ((lane >> 4) << 3);
    const int boff = (((lane >> 3) & 1) << 4);

    for (int kt = 0; kt < NKT; kt++) {
        if (kt + 1 < NKT) { load_stage(kt + 1); CP_WAIT1(); }
        else              { CP_WAIT0(); }
        __syncthreads();

        const int st = kt & 1;
        const uint32_t aBase = sbase + st * 16384;
        const uint32_t bBase = sbase + 32768 + st * 16384;

#pragma unroll
        for (int kk = 0; kk < 4; kk++) {
            uint32_t af[4][4], bf[4][4];
#pragma unroll
            for (int mt = 0; mt < 4; mt++)
                ldmatrix_x4(af[mt], aBase + SW128((uint32_t)((arow + mt * 16) * 128 + kk * 32 + aoff)));
#pragma unroll
            for (int nb = 0; nb < 4; nb++)
                ldmatrix_x4(bf[nb], bBase + SW128((uint32_t)((brow + nb * 16) * 128 + kk * 32 + boff)));
#pragma unroll
            for (int mt = 0; mt < 4; mt++)
#pragma unroll
                for (int np = 0; np < 8; np++)
                    mma16816(c[mt][np], af[mt], bf[np >> 1][(np & 1) * 2], bf[np >> 1][(np & 1) * 2 + 1]);
        }
        __syncthreads();
    }

    // ---- epilogue: per-row top-2 within this CTA's 128 columns ----
    float* sv1 = (float*)smem;                 // [128][2]
    int*   sm1 = (int*)(smem + 1024);          // [128][2]
    float* sv2 = (float*)(smem + 2048);        // [128][2]

#pragma unroll
    for (int mt = 0; mt < 4; mt++) {
#pragma unroll
        for (int p = 0; p < 2; p++) {
            float v1 = -1e30f, v2 = -1e30f;
            int mi = 0x7fffffff;
#pragma unroll
            for (int np = 0; np < 8; np++) {
#pragma unroll
                for (int q = 0; q < 2; q++) {
                    float v = c[mt][np][p * 2 + q];
                    int m = n0 + wn * 64 + np * 8 + (lane & 3) * 2 + q;
                    if (v > v1 || (v == v1 && m < mi)) { v2 = v1; v1 = v; mi = m; }
                    else if (v > v2) v2 = v;
                }
            }
#pragma unroll
            for (int o = 1; o <= 2; o <<= 1) {
                float ov1 = __shfl_xor_sync(0xffffffffu, v1, o);
                int   omi = __shfl_xor_sync(0xffffffffu, mi, o);
                float ov2 = __shfl_xor_sync(0xffffffffu, v2, o);
                if (ov1 > v1 || (ov1 == v1 && omi < mi)) {
                    v2 = fmaxf(v1, ov2); v1 = ov1; mi = omi;
                } else {
                    v2 = fmaxf(v2, ov1);
                }
            }
            if ((lane & 3) == 0) {
                int rloc = wm * 64 + mt * 16 + (lane >> 2) + p * 8;
                sv1[rloc * 2 + wn] = v1;
                sm1[rloc * 2 + wn] = mi;
                sv2[rloc * 2 + wn] = v2;
            }
        }
    }
    __syncthreads();

    {
        float v1 = sv1[tid * 2], v2 = sv2[tid * 2];
        int mi = sm1[tid * 2];
        float bv1 = sv1[tid * 2 + 1], bv2 = sv2[tid * 2 + 1];
        int bmi = sm1[tid * 2 + 1];
        if (bv1 > v1 || (bv1 == v1 && bmi < mi)) {
            v2 = fmaxf(v1, bv2); v1 = bv1; mi = bmi;
        } else {
            v2 = fmaxf(v2, bv1);
        }
        size_t slot = (size_t)(m0 + tid) * NBN + blockIdx.y;
        g_c1[slot] = ((unsigned long long)fkey(v1) << 32) | (unsigned int)(~(unsigned int)mi);
        g_c2[slot] = v2;
    }
}

// ---------------------------------------------------------------------------
// 3) merge per-row candidates (8 threads/row); flag tight rows and emit
//    (row, block) pairs for every block whose top1 is within MARGIN of v1
// ---------------------------------------------------------------------------
__global__ void merge_kernel() {
    int r = threadIdx.x >> 3, l = threadIdx.x & 7;
    int n = blockIdx.x * 32 + r;
    const unsigned long long* row1 = &g_c1[(size_t)n * NBN];
    const float* row2 = &g_c2[(size_t)n * NBN];

    unsigned long long k1 = 0ull;
#pragma unroll 3
    for (int j = l; j < NBN; j += 8) {
        unsigned long long k = row1[j];
        if (k > k1) k1 = k;
    }
#pragma unroll
    for (int o = 1; o <= 4; o <<= 1) {
        unsigned long long ok = __shfl_xor_sync(0xffffffffu, k1, o);
        if (ok > k1) k1 = ok;
    }
    unsigned int gi = ~(unsigned int)(k1 & 0xffffffffull);
    float gv1 = unfkey((unsigned int)(k1 >> 32));
    float v2 = -1e30f;
#pragma unroll 3
    for (int j = l; j < NBN; j += 8) {
        unsigned long long k = row1[j];
        unsigned int ij = ~(unsigned int)(k & 0xffffffffull);
        float cand = (ij == gi) ? row2[j] : unfkey((unsigned int)(k >> 32));
        if (cand > v2) v2 = cand;
    }
#pragma unroll
    for (int o = 1; o <= 4; o <<= 1)
        v2 = fmaxf(v2, __shfl_xor_sync(0xffffffffu, v2, o));

    bool flagged = (gv1 - v2 < MARGIN);
    if (l == 0) {
        g_idx[n] = (int)gi;
        if (flagged) {
            g_fix[n] = 0ull;
            int p = atomicAdd(&g_flagcnt, 1);
            g_flag[p] = n;
        }
    }
    if (flagged) {
        float thresh = gv1 - MARGIN;
#pragma unroll 3
        for (int j = l; j < NBN; j += 8) {
            float bt1 = unfkey((unsigned int)(row1[j] >> 32));
            if (bt1 >= thresh) {
                int p = atomicAdd(&g_paircnt, 1);
                g_pairs[p] = (n << 7) | j;
            }
        }
    }
}

// ---------------------------------------------------------------------------
// 4) candidate-block exact fp32 fixup: one (row, block) pair per iteration
// ---------------------------------------------------------------------------
__global__ void fixup_block_kernel() {
    const int cnt = g_paircnt;
    __shared__ float xs[DD];
    __shared__ unsigned long long red[128];

    for (int p = blockIdx.x; p < cnt; p += gridDim.x) {
        int pk = g_pairs[p];
        int n = pk >> 7, j = pk & 127;
        __syncthreads();                      // protect xs across iterations
        if (threadIdx.x < 64)
            *(float4*)&xs[threadIdx.x * 4] =
                *(const float4*)&g_xn[(size_t)n * DD + threadIdx.x * 4];
        __syncthreads();

        int m = j * 128 + threadIdx.x;
        const float4* yr = (const float4*)&g_yn[(size_t)m * DD];
        float s = 0.f;
#pragma unroll
        for (int d4 = 0; d4 < DD / 4; d4++) {
            float4 y = yr[d4];
            s = fmaf(xs[d4 * 4 + 0], y.x, s);
            s = fmaf(xs[d4 * 4 + 1], y.y, s);
            s = fmaf(xs[d4 * 4 + 2], y.z, s);
            s = fmaf(xs[d4 * 4 + 3], y.w, s);
        }
        red[threadIdx.x] = ((unsigned long long)fkey(s) << 32) |
                           (unsigned int)(~(unsigned int)m);
        __syncthreads();
#pragma unroll
        for (int k = 64; k; k >>= 1) {
            if (threadIdx.x < (unsigned)k && red[threadIdx.x + k] > red[threadIdx.x])
                red[threadIdx.x] = red[threadIdx.x + k];
            __syncthreads();
        }
        if (threadIdx.x == 0) atomicMax(&g_fix[n], red[0]);
    }
}

// ---------------------------------------------------------------------------
// 5) apply fixup results to g_idx
// ---------------------------------------------------------------------------
__global__ void fixup_apply_kernel() {
    int slot = blockIdx.x * 256 + threadIdx.x;
    if (slot < g_flagcnt) {
        int n = g_flag[slot];
        g_idx[n] = (int)(~(unsigned int)(g_fix[n] & 0xffffffffull));
    }
}

// ---------------------------------------------------------------------------
// 6) gather Y_sel (float4 in d) + per-block deterministic loss partials
//    Xf was already written by norm_all_kernel.
// ---------------------------------------------------------------------------
__global__ void gather_kernel(const float* __restrict__ xf,
                              float* __restrict__ ysel) {
    int g = blockIdx.x * 256 + threadIdx.x;
    int n  = g % NPIX;
    int d0 = (g / NPIX) * 4;
    int idx = g_idx[n];
    float4 y = *(const float4*)&g_yn[(size_t)idx * DD + d0];
    float sq = 0.f;
#pragma unroll
    for (int q = 0; q < 4; q++) {
        float ys = (&y.x)[q];
        float xv = xf[(size_t)(d0 + q) * NPIX + n];
        ysel[(size_t)(d0 + q) * NPIX + n] = ys;
        float dd = xv - ys;
        sq = fmaf(dd, dd, sq);
    }
#pragma unroll
    for (int off = 16; off; off >>= 1) sq += __shfl_xor_sync(0xffffffffu, sq, off);
    __shared__ float w[8];
    if ((threadIdx.x & 31) == 0) w[threadIdx.x >> 5] = sq;
    __syncthreads();
    if (threadIdx.x == 0) {
        float s = 0.f;
#pragma unroll
        for (int k = 0; k < 8; k++) s += w[k];
        g_bsum[blockIdx.x] = (double)s;
    }
}

// ---------------------------------------------------------------------------
// 7) deterministic final loss reduction
// ---------------------------------------------------------------------------
__global__ void finalize_kernel(float* __restrict__ out) {
    __shared__ double sm[256];
    double s = 0.0;
    const int NB = DD * NPIX / 1024;
    for (int i = threadIdx.x; i < NB; i += 256) s += g_bsum[i];
    sm[threadIdx.x] = s;
    __syncthreads();
    for (int k = 128; k; k >>= 1) {
        if (threadIdx.x < k) sm[threadIdx.x] += sm[threadIdx.x + k];
        __syncthreads();
    }
    if (threadIdx.x == 0) out[0] = (float)(sm[0] / (double)(DD * NPIX));
}

// ---------------------------------------------------------------------------
extern "C" void kernel_launch(void* const* d_in, const int* in_sizes, int n_in,
                              void* d_out, int out_size) {
    const float* X = (const float*)d_in[0];
    const float* Y = (const float*)d_in[1];
    // d_in[2], d_in[3] (images) are dead inputs.
    float* out    = (float*)d_out;
    float* ysel   = out + 1;
    float* xf_out = out + 1 + DD * NPIX;

    cudaFuncSetAttribute(simgemm_kernel,
                         cudaFuncAttributeMaxDynamicSharedMemorySize, SMEM_GEMM_BYTES);

    norm_all_kernel<<<dim3(NPIX / 32, 2), 256>>>(X, Y, xf_out);
    simgemm_kernel<<<dim3(NBM, NBN), 128, SMEM_GEMM_BYTES>>>();
    merge_kernel<<<NPIX / 32, 256>>>();
    fixup_block_kernel<<<1184, 128>>>();
    fixup_apply_kernel<<<NPIX / 256, 256>>>();
    gather_kernel<<<DD * NPIX / 1024, 256>>>(xf_out, ysel);
    finalize_kernel<<<1, 256>>>(out);
}

// round 10
// speedup vs baseline: 6.3981x; 1.3475x over previous
#include <cuda_runtime.h>
#include <cuda_fp16.h>
#include <cstdint>

#define DD   256
#define NPIX 9216
#define EPSF 2.220446049250313e-16f

#define BM 128
#define BN 128
#define BKH 64                   // fp16 per k-stage (= 128 bytes/row)
#define NKT (DD / BKH)           // 4
#define NBM (NPIX / BM)          // 72
#define NBN (NPIX / BN)          // 72
#define MARGIN 1.1e-3f           // > 2E, E = fp16 hi*hi screen error bound (~4.9e-4)

// ---------------- device scratch ----------------
__device__ __half g_A[(size_t)NPIX * DD];     // fp16(Xn) [n][256]
__device__ __half g_B[(size_t)NPIX * DD];     // fp16(Yn) [m][256]
__device__ float  g_xn[(size_t)NPIX * DD];    // normalized X [n][d]
__device__ float  g_yn[(size_t)NPIX * DD];    // normalized Y [m][d]
__device__ unsigned long long g_c1[(size_t)NPIX * NBN];
__device__ float  g_c2[(size_t)NPIX * NBN];
__device__ int    g_idx[NPIX];
__device__ int    g_flag[NPIX];
__device__ unsigned long long g_fix[NPIX];
__device__ int    g_flagcnt;
__device__ int    g_paircnt;
__device__ int    g_pairs[(size_t)NPIX * NBN / 8];   // (n<<7|j) worklist; ample
__device__ double g_bsum[DD * NPIX / 1024];

// ---------------- helpers ----------------
__device__ __forceinline__ uint32_t smem_u32(const void* p) {
    uint32_t a;
    asm("{ .reg .u64 t; cvta.to.shared.u64 t, %1; cvt.u32.u64 %0, t; }" : "=r"(a) : "l"(p));
    return a;
}
#define SW128(off) ((off) ^ (((off) >> 3) & 0x70))

__device__ __forceinline__ unsigned int fkey(float v) {
    unsigned int u = __float_as_uint(v);
    return (u & 0x80000000u) ? ~u : (u | 0x80000000u);
}
__device__ __forceinline__ float unfkey(unsigned int h) {
    return __uint_as_float((h & 0x80000000u) ? (h ^ 0x80000000u) : ~h);
}
__device__ __forceinline__ void cpasync16(uint32_t saddr, const void* g) {
    asm volatile("cp.async.cg.shared.global [%0], [%1], 16;" :: "r"(saddr), "l"(g));
}
#define CP_COMMIT() asm volatile("cp.async.commit_group;" ::: "memory")
#define CP_WAIT1()  asm volatile("cp.async.wait_group 1;" ::: "memory")
#define CP_WAIT0()  asm volatile("cp.async.wait_group 0;" ::: "memory")

__device__ __forceinline__ void ldmatrix_x4(uint32_t* r, uint32_t addr) {
    asm volatile("ldmatrix.sync.aligned.m8n8.x4.shared.b16 {%0,%1,%2,%3}, [%4];"
                 : "=r"(r[0]), "=r"(r[1]), "=r"(r[2]), "=r"(r[3]) : "r"(addr));
}
__device__ __forceinline__ void mma16816(float* c, const uint32_t* a, uint32_t b0, uint32_t b1) {
    asm volatile("mma.sync.aligned.m16n8k16.row.col.f32.f16.f16.f32 "
                 "{%0,%1,%2,%3}, {%4,%5,%6,%7}, {%8,%9}, {%0,%1,%2,%3};"
                 : "+f"(c[0]), "+f"(c[1]), "+f"(c[2]), "+f"(c[3])
                 : "r"(a[0]), "r"(a[1]), "r"(a[2]), "r"(a[3]), "r"(b0), "r"(b1));
}

// ---------------------------------------------------------------------------
// 1) fused: load 256d x 32n tile, compute inv-norms, emit normalized fp32+fp16
//    (transposed [n][d]) and, for X, the Xf output [d][n]. Resets counters.
// ---------------------------------------------------------------------------
__global__ void __launch_bounds__(256) norm_all_kernel(const float* __restrict__ X,
                                                       const float* __restrict__ Y,
                                                       float* __restrict__ xf_out) {
    __shared__ float s[256][33];     // [d][n_local], padded
    __shared__ float psum[8][32];
    __shared__ float ivs[32];
    const bool isB = (blockIdx.y != 0);
    const float* src = isB ? Y : X;
    float* dstf      = isB ? g_yn : g_xn;
    __half* dsth     = isB ? g_B : g_A;
    const int n0 = blockIdx.x * 32;
    const int tx = threadIdx.x & 31, ty = threadIdx.x >> 5;

    if (blockIdx.x == 0 && blockIdx.y == 0 && threadIdx.x == 0) {
        g_flagcnt = 0; g_paircnt = 0;
    }

    float acc = 0.f;
#pragma unroll
    for (int p = 0; p < 32; p++) {
        int d = ty * 32 + p;
        float v = src[(size_t)d * NPIX + n0 + tx];
        s[d][tx] = v;
        acc = fmaf(v, v, acc);
    }
    psum[ty][tx] = acc;
    __syncthreads();
    if (ty == 0) {
        float t = 0.f;
#pragma unroll
        for (int w = 0; w < 8; w++) t += psum[w][tx];
        ivs[tx] = 1.0f / (sqrtf(t) + EPSF);
    }
    __syncthreads();

    // transposed outputs [n][d], coalesced in d
#pragma unroll
    for (int nl = ty; nl < 32; nl += 8) {
        float iv = ivs[nl];
        size_t base = (size_t)(n0 + nl) * DD;
#pragma unroll
        for (int q = 0; q < 8; q++) {
            int d = q * 32 + tx;
            float v = s[d][nl] * iv;
            dstf[base + d] = v;
            dsth[base + d] = __float2half_rn(v);
        }
    }
    // Xf output [d][n], coalesced in n
    if (!isB) {
        float iv = ivs[tx];
#pragma unroll
        for (int p = 0; p < 32; p++) {
            int d = ty * 32 + p;
            xf_out[(size_t)d * NPIX + n0 + tx] = s[d][tx] * iv;
        }
    }
}

// ---------------------------------------------------------------------------
// 2) fp16 mma.sync GEMM (K=256, 128x128 tile, 4 warps of 64x64, occ 2)
//    + fused per-row top-2
// ---------------------------------------------------------------------------
#define SMEM_GEMM_BYTES 65536

__global__ void __launch_bounds__(128, 2) simgemm_kernel() {
    extern __shared__ char smem[];
    const uint32_t sbase = smem_u32(smem);
    const int tid  = threadIdx.x;
    const int wid  = tid >> 5;
    const int lane = tid & 31;
    const int wm   = wid & 1;
    const int wn   = wid >> 1;
    const int m0   = blockIdx.x * BM;
    const int n0   = blockIdx.y * BN;

    float c[4][8][4];
#pragma unroll
    for (int i = 0; i < 4; i++)
#pragma unroll
        for (int j = 0; j < 8; j++)
#pragma unroll
            for (int q = 0; q < 4; q++) c[i][j][q] = 0.f;

    auto load_stage = [&](int kt) {
        const int st = kt & 1;
        const int k0 = kt * BKH;
#pragma unroll
        for (int it = 0; it < 8; it++) {
            int i = tid + it * 128;
            int r = i >> 3, cb = (i & 7) << 4;
            uint32_t sa = sbase + st * 16384 + SW128((uint32_t)(r * 128 + cb));
            const char* ga = (const char*)g_A + ((size_t)(m0 + r) * DD + k0) * 2 + cb;
            cpasync16(sa, ga);
        }
#pragma unroll
        for (int it = 0; it < 8; it++) {
            int i = tid + it * 128;
            int r = i >> 3, cb = (i & 7) << 4;
            uint32_t sa = sbase + 32768 + st * 16384 + SW128((uint32_t)(r * 128 + cb));
            const char* gb = (const char*)g_B + ((size_t)(n0 + r) * DD + k0) * 2 + cb;
            cpasync16(sa, gb);
        }
        CP_COMMIT();
    };

    load_stage(0);

    const int arow = wm * 64 + (lane & 15);
    const int aoff = ((lane >> 4) << 4);
    const int brow = wn * 64 + (lane & 7) + ((lane >> 4) << 3);
    const int boff = (((lane >> 3) & 1) << 4);

    for (int kt = 0; kt < NKT; kt++) {
        if (kt + 1 < NKT) { load_stage(kt + 1); CP_WAIT1(); }
        else              { CP_WAIT0(); }
        __syncthreads();

        const int st = kt & 1;
        const uint32_t aBase = sbase + st * 16384;
        const uint32_t bBase = sbase + 32768 + st * 16384;

#pragma unroll
        for (int kk = 0; kk < 4; kk++) {
            uint32_t af[4][4], bf[4][4];
#pragma unroll
            for (int mt = 0; mt < 4; mt++)
                ldmatrix_x4(af[mt], aBase + SW128((uint32_t)((arow + mt * 16) * 128 + kk * 32 + aoff)));
#pragma unroll
            for (int nb = 0; nb < 4; nb++)
                ldmatrix_x4(bf[nb], bBase + SW128((uint32_t)((brow + nb * 16) * 128 + kk * 32 + boff)));
#pragma unroll
            for (int mt = 0; mt < 4; mt++)
#pragma unroll
                for (int np = 0; np < 8; np++)
                    mma16816(c[mt][np], af[mt], bf[np >> 1][(np & 1) * 2], bf[np >> 1][(np & 1) * 2 + 1]);
        }
        __syncthreads();
    }

    // ---- epilogue: per-row top-2 within this CTA's 128 columns ----
    float* sv1 = (float*)smem;                 // [128][2]
    int*   sm1 = (int*)(smem + 1024);          // [128][2]
    float* sv2 = (float*)(smem + 2048);        // [128][2]

#pragma unroll
    for (int mt = 0; mt < 4; mt++) {
#pragma unroll
        for (int p = 0; p < 2; p++) {
            float v1 = -1e30f, v2 = -1e30f;
            int mi = 0x7fffffff;
#pragma unroll
            for (int np = 0; np < 8; np++) {
#pragma unroll
                for (int q = 0; q < 2; q++) {
                    float v = c[mt][np][p * 2 + q];
                    int m = n0 + wn * 64 + np * 8 + (lane & 3) * 2 + q;
                    if (v > v1 || (v == v1 && m < mi)) { v2 = v1; v1 = v; mi = m; }
                    else if (v > v2) v2 = v;
                }
            }
#pragma unroll
            for (int o = 1; o <= 2; o <<= 1) {
                float ov1 = __shfl_xor_sync(0xffffffffu, v1, o);
                int   omi = __shfl_xor_sync(0xffffffffu, mi, o);
                float ov2 = __shfl_xor_sync(0xffffffffu, v2, o);
                if (ov1 > v1 || (ov1 == v1 && omi < mi)) {
                    v2 = fmaxf(v1, ov2); v1 = ov1; mi = omi;
                } else {
                    v2 = fmaxf(v2, ov1);
                }
            }
            if ((lane & 3) == 0) {
                int rloc = wm * 64 + mt * 16 + (lane >> 2) + p * 8;
                sv1[rloc * 2 + wn] = v1;
                sm1[rloc * 2 + wn] = mi;
                sv2[rloc * 2 + wn] = v2;
            }
        }
    }
    __syncthreads();

    {
        float v1 = sv1[tid * 2], v2 = sv2[tid * 2];
        int mi = sm1[tid * 2];
        float bv1 = sv1[tid * 2 + 1], bv2 = sv2[tid * 2 + 1];
        int bmi = sm1[tid * 2 + 1];
        if (bv1 > v1 || (bv1 == v1 && bmi < mi)) {
            v2 = fmaxf(v1, bv2); v1 = bv1; mi = bmi;
        } else {
            v2 = fmaxf(v2, bv1);
        }
        size_t slot = (size_t)(m0 + tid) * NBN + blockIdx.y;
        g_c1[slot] = ((unsigned long long)fkey(v1) << 32) | (unsigned int)(~(unsigned int)mi);
        g_c2[slot] = v2;
    }
}

// ---------------------------------------------------------------------------
// 3) merge per-row candidates (8 threads/row); flag tight rows and emit
//    (row, block) pairs for every block whose top1 is within MARGIN of v1
// ---------------------------------------------------------------------------
__global__ void merge_kernel() {
    int r = threadIdx.x >> 3, l = threadIdx.x & 7;
    int n = blockIdx.x * 32 + r;
    const unsigned long long* row1 = &g_c1[(size_t)n * NBN];
    const float* row2 = &g_c2[(size_t)n * NBN];

    unsigned long long k1 = 0ull;
#pragma unroll 3
    for (int j = l; j < NBN; j += 8) {
        unsigned long long k = row1[j];
        if (k > k1) k1 = k;
    }
#pragma unroll
    for (int o = 1; o <= 4; o <<= 1) {
        unsigned long long ok = __shfl_xor_sync(0xffffffffu, k1, o);
        if (ok > k1) k1 = ok;
    }
    unsigned int gi = ~(unsigned int)(k1 & 0xffffffffull);
    float gv1 = unfkey((unsigned int)(k1 >> 32));
    float v2 = -1e30f;
#pragma unroll 3
    for (int j = l; j < NBN; j += 8) {
        unsigned long long k = row1[j];
        unsigned int ij = ~(unsigned int)(k & 0xffffffffull);
        float cand = (ij == gi) ? row2[j] : unfkey((unsigned int)(k >> 32));
        if (cand > v2) v2 = cand;
    }
#pragma unroll
    for (int o = 1; o <= 4; o <<= 1)
        v2 = fmaxf(v2, __shfl_xor_sync(0xffffffffu, v2, o));

    bool flagged = (gv1 - v2 < MARGIN);
    if (l == 0) {
        g_idx[n] = (int)gi;
        if (flagged) {
            g_fix[n] = 0ull;
            int p = atomicAdd(&g_flagcnt, 1);
            g_flag[p] = n;
        }
    }
    if (flagged) {
        float thresh = gv1 - MARGIN;
#pragma unroll 3
        for (int j = l; j < NBN; j += 8) {
            float bt1 = unfkey((unsigned int)(row1[j] >> 32));
            if (bt1 >= thresh) {
                int p = atomicAdd(&g_paircnt, 1);
                g_pairs[p] = (n << 7) | j;
            }
        }
    }
}

// ---------------------------------------------------------------------------
// 4) candidate-block exact fp32 fixup, warp-per-m coalesced:
//    lanes own 8-float d-slices; 4 m's per batch; butterfly reduce
// ---------------------------------------------------------------------------
__global__ void __launch_bounds__(128) fixup_block_kernel() {
    const int cnt = g_paircnt;
    const int wid = threadIdx.x >> 5, lane = threadIdx.x & 31;

    for (int p = blockIdx.x; p < cnt; p += gridDim.x) {
        int pk = g_pairs[p];
        int n = pk >> 7, j = pk & 127;

        const float4* xr = (const float4*)&g_xn[(size_t)n * DD + lane * 8];
        float4 xa = xr[0], xb = xr[1];

        unsigned long long best = 0ull;
        const int m_base = j * 128 + wid * 32;
#pragma unroll 2
        for (int i = 0; i < 32; i += 4) {
            float s[4];
#pragma unroll
            for (int b = 0; b < 4; b++) {
                const float4* yr = (const float4*)&g_yn[(size_t)(m_base + i + b) * DD + lane * 8];
                float4 ya = yr[0], yb = yr[1];
                float t;
                t = xa.x * ya.x;
                t = fmaf(xa.y, ya.y, t);
                t = fmaf(xa.z, ya.z, t);
                t = fmaf(xa.w, ya.w, t);
                t = fmaf(xb.x, yb.x, t);
                t = fmaf(xb.y, yb.y, t);
                t = fmaf(xb.z, yb.z, t);
                t = fmaf(xb.w, yb.w, t);
                s[b] = t;
            }
#pragma unroll
            for (int off = 16; off; off >>= 1) {
#pragma unroll
                for (int b = 0; b < 4; b++)
                    s[b] += __shfl_xor_sync(0xffffffffu, s[b], off);
            }
#pragma unroll
            for (int b = 0; b < 4; b++) {
                unsigned int m = (unsigned int)(m_base + i + b);
                unsigned long long k = ((unsigned long long)fkey(s[b]) << 32) |
                                       (unsigned int)(~m);
                if (k > best) best = k;
            }
        }
        if (lane == 0) atomicMax(&g_fix[n], best);
    }
}

// ---------------------------------------------------------------------------
// 5) apply fixup results to g_idx
// ---------------------------------------------------------------------------
__global__ void fixup_apply_kernel() {
    int slot = blockIdx.x * 256 + threadIdx.x;
    if (slot < g_flagcnt) {
        int n = g_flag[slot];
        g_idx[n] = (int)(~(unsigned int)(g_fix[n] & 0xffffffffull));
    }
}

// ---------------------------------------------------------------------------
// 6) gather Y_sel (float4 in d) + per-block deterministic loss partials
// ---------------------------------------------------------------------------
__global__ void gather_kernel(const float* __restrict__ xf,
                              float* __restrict__ ysel) {
    int g = blockIdx.x * 256 + threadIdx.x;
    int n  = g % NPIX;
    int d0 = (g / NPIX) * 4;
    int idx = g_idx[n];
    float4 y = *(const float4*)&g_yn[(size_t)idx * DD + d0];
    float sq = 0.f;
#pragma unroll
    for (int q = 0; q < 4; q++) {
        float ys = (&y.x)[q];
        float xv = xf[(size_t)(d0 + q) * NPIX + n];
        ysel[(size_t)(d0 + q) * NPIX + n] = ys;
        float dd = xv - ys;
        sq = fmaf(dd, dd, sq);
    }
#pragma unroll
    for (int off = 16; off; off >>= 1) sq += __shfl_xor_sync(0xffffffffu, sq, off);
    __shared__ float w[8];
    if ((threadIdx.x & 31) == 0) w[threadIdx.x >> 5] = sq;
    __syncthreads();
    if (threadIdx.x == 0) {
        float s = 0.f;
#pragma unroll
        for (int k = 0; k < 8; k++) s += w[k];
        g_bsum[blockIdx.x] = (double)s;
    }
}

// ---------------------------------------------------------------------------
// 7) deterministic final loss reduction
// ---------------------------------------------------------------------------
__global__ void finalize_kernel(float* __restrict__ out) {
    __shared__ double sm[256];
    double s = 0.0;
    const int NB = DD * NPIX / 1024;
    for (int i = threadIdx.x; i < NB; i += 256) s += g_bsum[i];
    sm[threadIdx.x] = s;
    __syncthreads();
    for (int k = 128; k; k >>= 1) {
        if (threadIdx.x < k) sm[threadIdx.x] += sm[threadIdx.x + k];
        __syncthreads();
    }
    if (threadIdx.x == 0) out[0] = (float)(sm[0] / (double)(DD * NPIX));
}

// ---------------------------------------------------------------------------
extern "C" void kernel_launch(void* const* d_in, const int* in_sizes, int n_in,
                              void* d_out, int out_size) {
    const float* X = (const float*)d_in[0];
    const float* Y = (const float*)d_in[1];
    // d_in[2], d_in[3] (images) are dead inputs.
    float* out    = (float*)d_out;
    float* ysel   = out + 1;
    float* xf_out = out + 1 + DD * NPIX;

    cudaFuncSetAttribute(simgemm_kernel,
                         cudaFuncAttributeMaxDynamicSharedMemorySize, SMEM_GEMM_BYTES);

    norm_all_kernel<<<dim3(NPIX / 32, 2), 256>>>(X, Y, xf_out);
    simgemm_kernel<<<dim3(NBM, NBN), 128, SMEM_GEMM_BYTES>>>();
    merge_kernel<<<NPIX / 32, 256>>>();
    fixup_block_kernel<<<1184, 128>>>();
    fixup_apply_kernel<<<NPIX / 256, 256>>>();
    gather_kernel<<<DD * NPIX / 1024, 256>>>(xf_out, ysel);
    finalize_kernel<<<1, 256>>>(out);
}